// round 13
// baseline (speedup 1.0000x reference)
#include <cuda_runtime.h>
#include <math.h>
#include <stdint.h>

#define Hh 12
#define NRr 512
#define NNt 768
#define C1c 384
#define C2c 128
#define WC_ 0.23570226039551584f   /* sqrt(1/18) */
#define WLS 0.14433756729740643f   /* sqrt(1/3)/4 */

#define JH   384                   /* j per half (per k_att CTA) */
#define TJ   64                    /* j rows per tile */
#define WP2  392                   /* Wt row pad */
#define PADc 132                   /* rep tile row pad */
#define WQP  16                    /* wq row pad */
#define PP2  68                    /* psm row pad */

static __device__ float g_raw[(size_t)NNt*1152];
static __device__ float g_R[NNt*9];
static __device__ float g_t[NNt*3];
static __device__ float g_q[(size_t)NNt*Hh*32];
static __device__ float g_kT[(size_t)Hh*32*NNt];
static __device__ float g_vph[(size_t)Hh*NNt*24];
static __device__ float g_W[(size_t)NNt*Hh*NNt];
static __device__ float g_og[(size_t)NNt*24*Hh];
static __device__ float g_feat[(size_t)NNt*2112];
static __device__ float g_fin[4][(size_t)NNt*C1c];
static __device__ float g_o2p[(size_t)2*NNt*2048];
static __device__ float g_ms[NNt*48];
static __device__ float g_fac[NNt*24];

__device__ __forceinline__ void cp16(float* dst, const float* src){
  unsigned sa=(unsigned)__cvta_generic_to_shared(dst);
  asm volatile("cp.async.cg.shared.global [%0], [%1], 16;\n" :: "r"(sa), "l"(src));
}
__device__ __forceinline__ uint32_t f2tf(float x){
  uint32_t r; asm("cvt.rna.tf32.f32 %0, %1;\n" : "=r"(r) : "f"(x)); return r;
}
__device__ __forceinline__ float f2tff(float x){
  uint32_t r; asm("cvt.rna.tf32.f32 %0, %1;\n" : "=r"(r) : "f"(x)); return __uint_as_float(r);
}
__device__ __forceinline__ void mma_tf32(float& d0,float& d1,float& d2,float& d3,
    uint32_t a0,uint32_t a1,uint32_t a2,uint32_t a3,uint32_t b0,uint32_t b1){
  asm volatile("mma.sync.aligned.m16n8k8.row.col.f32.tf32.tf32.f32 "
    "{%0,%1,%2,%3},{%4,%5,%6,%7},{%8,%9},{%0,%1,%2,%3};\n"
    : "+f"(d0),"+f"(d1),"+f"(d2),"+f"(d3)
    : "r"(a0),"r"(a1),"r"(a2),"r"(a3),"r"(b0),"r"(b1));
}

// ---------------- projections (tf32 mma): raw[768][1152] = X @ W ----------------
__global__ void k_proj(const float* __restrict__ rec1d, const float* __restrict__ lig1d,
                       const float* __restrict__ rw1, const float* __restrict__ rwp,
                       const float* __restrict__ lw1, const float* __restrict__ lwp){
  __shared__ float As[16][72], Bs[16][72];
  int m0=blockIdx.y*64, n0=blockIdx.x*64, tid=threadIdx.x;
  int wid=tid>>5, lane=tid&31, g=lane>>2, tg=lane&3;
  int mw=(wid&3)*16, nw=(wid>>2)*32;
  const float* X  = (m0<NRr)? rec1d+(size_t)m0*C1c : lig1d+(size_t)(m0-NRr)*C1c;
  const float* Bm = (m0<NRr)? ((n0<576)? rw1: rwp) : ((n0<576)? lw1: lwp);
  int nb = (n0<576)? n0 : n0-576;
  float acc[4][4]={};
  for(int k0=0;k0<C1c;k0+=16){
    for(int l=tid;l<1024;l+=256){ int kk=l&15,mm=l>>4; As[kk][mm]=f2tff(X[(size_t)mm*C1c+k0+kk]); }
    for(int l=tid;l<1024;l+=256){ int nn=l&63,kk=l>>6; Bs[kk][nn]=f2tff(Bm[(size_t)(k0+kk)*576+nb+nn]); }
    __syncthreads();
    #pragma unroll
    for(int ks=0;ks<16;ks+=8){
      uint32_t a0=__float_as_uint(As[ks+tg  ][mw+g  ]);
      uint32_t a1=__float_as_uint(As[ks+tg  ][mw+g+8]);
      uint32_t a2=__float_as_uint(As[ks+tg+4][mw+g  ]);
      uint32_t a3=__float_as_uint(As[ks+tg+4][mw+g+8]);
      #pragma unroll
      for(int blk=0;blk<4;blk++){
        uint32_t b0=__float_as_uint(Bs[ks+tg  ][nw+blk*8+g]);
        uint32_t b1=__float_as_uint(Bs[ks+tg+4][nw+blk*8+g]);
        mma_tf32(acc[blk][0],acc[blk][1],acc[blk][2],acc[blk][3],a0,a1,a2,a3,b0,b1);
      }
    }
    __syncthreads();
  }
  #pragma unroll
  for(int blk=0;blk<4;blk++){
    int r0=m0+mw+g, c=n0+nw+blk*8+tg*2;
    g_raw[(size_t)r0*1152+c]    =acc[blk][0];
    g_raw[(size_t)r0*1152+c+1]  =acc[blk][1];
    g_raw[(size_t)(r0+8)*1152+c]  =acc[blk][2];
    g_raw[(size_t)(r0+8)*1152+c+1]=acc[blk][3];
  }
}

// ---------------- frames: R,t, point transform, build q/k vectors & vph ----------------
__global__ void k_frame(const float* __restrict__ recT, const float* __restrict__ ligT){
  int i=blockIdx.x, d=threadIdx.x;           // 192 threads, d = h*16+e
  __shared__ float k2p[12][4];
  const float* T=(i<NRr)? recT+(size_t)i*7 : ligT+(size_t)(i-NRr)*7;
  float qw=T[0],qx=T[1],qy=T[2],qz=T[3];
  float inr=rsqrtf(qw*qw+qx*qx+qy*qy+qz*qz);
  qw*=inr;qx*=inr;qy*=inr;qz*=inr;
  float R[9];
  R[0]=1.f-2.f*(qy*qy+qz*qz); R[1]=2.f*(qx*qy-qw*qz); R[2]=2.f*(qx*qz+qw*qy);
  R[3]=2.f*(qx*qy+qw*qz); R[4]=1.f-2.f*(qx*qx+qz*qz); R[5]=2.f*(qy*qz-qw*qx);
  R[6]=2.f*(qx*qz-qw*qy); R[7]=2.f*(qy*qz+qw*qx); R[8]=1.f-2.f*(qx*qx+qy*qy);
  float t0=T[4],t1=T[5],t2=T[6];
  if(d<9) g_R[i*9+d]=R[d];
  if(d<3) g_t[i*3+d]=(d==0?t0:(d==1?t1:t2));
  const float* rp=g_raw+(size_t)i*1152+576;
  float l0=rp[d], l1=rp[192+d], l2=rp[384+d];
  float g0=R[0]*l0+R[1]*l1+R[2]*l2+t0;
  float g1=R[3]*l0+R[4]*l1+R[5]*l2+t1;
  float g2=R[6]*l0+R[7]*l1+R[8]*l2+t2;
  int h=d>>4, e=d&15;
  if(e<4){                                   // k-points
    k2p[h][e]=g0*g0+g1*g1+g2*g2;
    g_kT[(size_t)(h*32+0+e)*NNt+i]=g0;
    g_kT[(size_t)(h*32+4+e)*NNt+i]=g1;
    g_kT[(size_t)(h*32+8+e)*NNt+i]=g2;
  } else if(e<8){                            // q-points (pre-scaled)
    int p=e-4;
    float* q=&g_q[((size_t)i*Hh+h)*32];
    q[0+p]=2.f*WC_*g0; q[4+p]=2.f*WC_*g1; q[8+p]=2.f*WC_*g2;
  } else {                                   // v-points
    int p=e-8;
    float* v=&g_vph[((size_t)h*NNt+i)*24];
    v[p]=g0; v[8+p]=g1; v[16+p]=g2;
  }
  __syncthreads();
  const float* r1=g_raw+(size_t)i*1152;
  int s=e;
  g_kT[(size_t)(h*32+12+s)*NNt+i]=r1[h*48+s];            // k1
  g_q[((size_t)i*Hh+h)*32+12+s]=WLS*r1[h*48+16+s];       // q1 (pre-scaled)
  if(s==0){
    float K2=k2p[h][0]+k2p[h][1]+k2p[h][2]+k2p[h][3];
    g_kT[(size_t)(h*32+28)*NNt+i]=-WC_*K2;
    g_q[((size_t)i*Hh+h)*32+28]=1.f;
  } else if(s<4){
    g_kT[(size_t)(h*32+28+s)*NNt+i]=0.f;
    g_q[((size_t)i*Hh+h)*32+28+s]=0.f;
  }
}

// ------- qk logits (tf32 mma, hi/lo compensated) + coalesced smem-staged store -------
__global__ void k_qk(){
  __shared__ float qsm[4*2304];              // Ahi|Alo|Bhi|Blo, reused as store tile
  float* Ahi=qsm; float* Alo=qsm+2304; float* Bhi=qsm+4608; float* Blo=qsm+6912;
  int j0=blockIdx.x*64, i0=blockIdx.y*64, h=blockIdx.z, tid=threadIdx.x;
  int wid=tid>>5, lane=tid&31, g=lane>>2, tg=lane&3;
  int mw=(wid&3)*16, nw=(wid>>2)*32;
  for(int l=tid;l<2048;l+=256){ int kk=l&31, mm=l>>5;
    float v=g_q[((size_t)(i0+mm)*Hh+h)*32+kk];
    float hi=f2tff(v);
    Ahi[kk*72+mm]=hi; Alo[kk*72+mm]=f2tff(v-hi); }
  for(int l=tid;l<2048;l+=256){ int kk=l>>6, nn=l&63;
    float v=g_kT[(size_t)(h*32+kk)*NNt + j0+nn];
    float hi=f2tff(v);
    Bhi[kk*72+nn]=hi; Blo[kk*72+nn]=f2tff(v-hi); }
  __syncthreads();
  float acc[4][4]={};
  #pragma unroll
  for(int ks=0;ks<32;ks+=8){
    uint32_t ah0=__float_as_uint(Ahi[(ks+tg  )*72+mw+g  ]);
    uint32_t ah1=__float_as_uint(Ahi[(ks+tg  )*72+mw+g+8]);
    uint32_t ah2=__float_as_uint(Ahi[(ks+tg+4)*72+mw+g  ]);
    uint32_t ah3=__float_as_uint(Ahi[(ks+tg+4)*72+mw+g+8]);
    uint32_t al0=__float_as_uint(Alo[(ks+tg  )*72+mw+g  ]);
    uint32_t al1=__float_as_uint(Alo[(ks+tg  )*72+mw+g+8]);
    uint32_t al2=__float_as_uint(Alo[(ks+tg+4)*72+mw+g  ]);
    uint32_t al3=__float_as_uint(Alo[(ks+tg+4)*72+mw+g+8]);
    #pragma unroll
    for(int blk=0;blk<4;blk++){
      uint32_t bh0=__float_as_uint(Bhi[(ks+tg  )*72+nw+blk*8+g]);
      uint32_t bh1=__float_as_uint(Bhi[(ks+tg+4)*72+nw+blk*8+g]);
      uint32_t bl0=__float_as_uint(Blo[(ks+tg  )*72+nw+blk*8+g]);
      uint32_t bl1=__float_as_uint(Blo[(ks+tg+4)*72+nw+blk*8+g]);
      mma_tf32(acc[blk][0],acc[blk][1],acc[blk][2],acc[blk][3],ah0,ah1,ah2,ah3,bl0,bl1);
      mma_tf32(acc[blk][0],acc[blk][1],acc[blk][2],acc[blk][3],al0,al1,al2,al3,bh0,bh1);
      mma_tf32(acc[blk][0],acc[blk][1],acc[blk][2],acc[blk][3],ah0,ah1,ah2,ah3,bh0,bh1);
    }
  }
  __syncthreads();                            // all fragment reads done; reuse qsm
  float* S=qsm;                               // [64][65]
  #pragma unroll
  for(int blk=0;blk<4;blk++){
    int r0=mw+g, c=nw+blk*8+tg*2;
    S[r0*65+c]    =acc[blk][0]; S[r0*65+c+1]    =acc[blk][1];
    S[(r0+8)*65+c]=acc[blk][2]; S[(r0+8)*65+c+1]=acc[blk][3];
  }
  __syncthreads();
  for(int l=tid;l<1024;l+=256){ int r=l>>4, c4=(l&15)*4;
    float4 v=make_float4(S[r*65+c4],S[r*65+c4+1],S[r*65+c4+2],S[r*65+c4+3]);
    *(float4*)&g_W[((size_t)(i0+r)*Hh+h)*NNt + j0 + c4] = v;
  }
}

// ---- fused half-row attention: bias + partial online softmax + partial o_2d ----
// grid (2,768). 64-row tiles, double-buffered, 2 CTAs/SM, single-phase bias accum.
__global__ void __launch_bounds__(512,2) k_att(const float* __restrict__ rep,
                      const float* __restrict__ rr, const float* __restrict__ ll,
                      const float* __restrict__ rl, const float* __restrict__ lr){
  extern __shared__ float sm[];
  float* Wt   = sm;                        // [12][WP2]
  float* reps0= Wt + 12*WP2;               // [64][PADc]
  float* reps1= reps0 + 64*PADc;           // [64][PADc]
  float* wq   = reps1 + 64*PADc;           // [2][128][WQP]
  float* psm  = wq + 2*128*WQP;            // [16][PP2]
  float* ctrl = psm + 16*PP2;              // m[16], s[16], sc[16]
  float* sm_m = ctrl; float* sm_s = ctrl+16; float* sm_sc = ctrl+32;
  float* Wt2  = ctrl + 48;                 // [12][68] per-tile K-half-1 partials
  int half=blockIdx.x, i=blockIdx.y, tid=threadIdx.x;
  int jbase = half*JH;
  const float* wA = (i<NRr)? rr : lr;      // j < 512
  const float* wB = (i<NRr)? rl : ll;      // j >= 512
  // prologue: prefetch tiles 0 and 1
  {
    const float* rb = rep + ((size_t)i*NNt + jbase)*C2c;
    #pragma unroll
    for(int k=0;k<4;k++){ int l=tid+512*k; int jj=l>>5, c4=(l&31)*4;
      cp16(&reps0[jj*PADc+c4], rb + (size_t)jj*C2c + c4); }
    asm volatile("cp.async.commit_group;\n");
    rb += (size_t)TJ*C2c;
    #pragma unroll
    for(int k=0;k<4;k++){ int l=tid+512*k; int jj=l>>5, c4=(l&31)*4;
      cp16(&reps1[jj*PADc+c4], rb + (size_t)jj*C2c + c4); }
    asm volatile("cp.async.commit_group;\n");
  }
  if(tid<16){ sm_m[tid]=(tid<12)?-1e30f:0.f; sm_s[tid]=(tid<12)?0.f:1.f; sm_sc[tid]=1.f; }
  for(int l=tid;l<2*128*WQP;l+=512){
    int q=l/(128*WQP), rem=l%(128*WQP), c=rem/WQP, h=rem%WQP;
    float v = (h<12)? ((q==0)? wA[c*12+h] : wB[c*12+h]) : 0.f;
    wq[l]=__uint_as_float(f2tf(v));
  }
  for(int l=tid;l<16*PP2;l+=512) psm[l]=0.f;
  for(int l=tid;l<1152;l+=512){ int h=l/96, j4=(l%96)*4;
    *(float4*)&Wt[h*WP2+j4] = *(const float4*)&g_W[((size_t)i*Hh+h)*NNt + jbase + j4]; }

  int wid=tid>>5, lane=tid&31, g=lane>>2, tg=lane&3;
  int m0=(wid&3)*16, n0=((wid>>2)&1)*8, kb=(wid>>3)*64;   // bias mapping (K split)
  int cb0=wid*8;                                          // o2d mapping
  float o0=0.f,o1=0.f,o2=0.f,o3=0.f;

  for(int t=0;t<6;t++){
    float* rp = (t&1)? reps1 : reps0;
    if(t<5) asm volatile("cp.async.wait_group 1;\n");
    else    asm volatile("cp.async.wait_group 0;\n");
    __syncthreads();
    // ---- bias mma: K-half 0 adds into Wt, K-half 1 writes Wt2 (no serialization) ----
    {
      const float* wqs = wq + ((jbase + t*TJ >= NRr)? 128*WQP : 0);
      float c0=0.f,c1=0.f,c2=0.f,c3=0.f;
      #pragma unroll
      for(int k=0;k<8;k++){
        int k0=kb+k*8;
        uint32_t a0=__float_as_uint(rp[(m0+g  )*PADc + k0+tg  ]);
        uint32_t a1=__float_as_uint(rp[(m0+g+8)*PADc + k0+tg  ]);
        uint32_t a2=__float_as_uint(rp[(m0+g  )*PADc + k0+tg+4]);
        uint32_t a3=__float_as_uint(rp[(m0+g+8)*PADc + k0+tg+4]);
        uint32_t b0=__float_as_uint(wqs[(k0+tg  )*WQP + n0+g]);
        uint32_t b1=__float_as_uint(wqs[(k0+tg+4)*WQP + n0+g]);
        mma_tf32(c0,c1,c2,c3,a0,a1,a2,a3,b0,b1);
      }
      int h0=n0+tg*2, h1=h0+1, j0l=m0+g, j1l=m0+g+8;
      if(wid<8){
        if(h0<12){ Wt[h0*WP2+t*TJ+j0l]+=c0; Wt[h0*WP2+t*TJ+j1l]+=c2; }
        if(h1<12){ Wt[h1*WP2+t*TJ+j0l]+=c1; Wt[h1*WP2+t*TJ+j1l]+=c3; }
      } else {
        if(h0<12){ Wt2[h0*68+j0l]=c0; Wt2[h0*68+j1l]=c2; }
        if(h1<12){ Wt2[h1*68+j0l]=c1; Wt2[h1*68+j1l]=c3; }
      }
    }
    __syncthreads();
    // ---- online softmax (warp per head, 64 cols): merge Wt+Wt2, write back ----
    if(wid<12){
      float v[2]; float tmax=-1e30f;
      #pragma unroll
      for(int k=0;k<2;k++){
        v[k]=Wt[wid*WP2+t*TJ+lane+32*k]+Wt2[wid*68+lane+32*k];
        Wt[wid*WP2+t*TJ+lane+32*k]=v[k];
        tmax=fmaxf(tmax,v[k]); }
      #pragma unroll
      for(int o=16;o;o>>=1) tmax=fmaxf(tmax,__shfl_xor_sync(0xffffffffu,tmax,o));
      float mold=sm_m[wid], mnew=fmaxf(mold,tmax);
      float ps=0.f;
      #pragma unroll
      for(int k=0;k<2;k++){ float p=__expf(v[k]-mnew);
        psm[wid*PP2+lane+32*k]=__uint_as_float(f2tf(p)); ps+=p; }
      #pragma unroll
      for(int o=16;o;o>>=1) ps+=__shfl_xor_sync(0xffffffffu,ps,o);
      if(lane==0){ float sc=__expf(mold-mnew); sm_sc[wid]=sc; sm_m[wid]=mnew; sm_s[wid]=sm_s[wid]*sc+ps; }
    }
    __syncthreads();
    // ---- o2d mma: rescale then accumulate (K=64) ----
    {
      float s_lo=sm_sc[g], s_hi=sm_sc[g+8];
      o0*=s_lo; o1*=s_lo; o2*=s_hi; o3*=s_hi;
      #pragma unroll
      for(int k=0;k<8;k++){
        int k0=k*8;
        uint32_t a0=__float_as_uint(psm[(g  )*PP2 + k0+tg  ]);
        uint32_t a1=__float_as_uint(psm[(g+8)*PP2 + k0+tg  ]);
        uint32_t a2=__float_as_uint(psm[(g  )*PP2 + k0+tg+4]);
        uint32_t a3=__float_as_uint(psm[(g+8)*PP2 + k0+tg+4]);
        uint32_t b0=__float_as_uint(rp[(k0+tg  )*PADc + cb0+g]);
        uint32_t b1=__float_as_uint(rp[(k0+tg+4)*PADc + cb0+g]);
        mma_tf32(o0,o1,o2,o3,a0,a1,a2,a3,b0,b1);
      }
    }
    __syncthreads();
    // ---- prefetch tile t+2 into this tile's (now free) buffer ----
    if(t<4){
      const float* rb = rep + ((size_t)i*NNt + jbase + (t+2)*TJ)*C2c;
      #pragma unroll
      for(int k=0;k<4;k++){ int l=tid+512*k; int jj=l>>5, c4=(l&31)*4;
        cp16(&rp[jj*PADc+c4], rb + (size_t)jj*C2c + c4); }
      asm volatile("cp.async.commit_group;\n");
    }
  }
  // ---- partial outputs ----
  if(tid<12){
    g_ms[(size_t)i*48 + tid*4 + half*2 + 0]=sm_m[tid];
    g_ms[(size_t)i*48 + tid*4 + half*2 + 1]=sm_s[tid];
  }
  {
    int cc=cb0+tg*2;
    float* ob = g_o2p + ((size_t)(half*NNt+i))*2048;
    ob[g*128+cc]=o0; ob[g*128+cc+1]=o1;
    ob[(g+8)*128+cc]=o2; ob[(g+8)*128+cc+1]=o3;
  }
  for(int l=tid;l<4608;l+=512){ int h=l/JH, jl=l-h*JH;
    g_W[((size_t)i*Hh+h)*NNt + jbase + jl] = __expf(Wt[h*WP2+jl]-sm_m[h]);
  }
}

// ---- combine halves: softmax factors + final o_2d -> g_feat[0:1536], g_fac ----
__global__ void k_comb2(){
  int i=blockIdx.x, tid=threadIdx.x;      // 256 threads
  __shared__ float ff[12][2];
  if(tid<12){
    float m0=g_ms[(size_t)i*48+tid*4+0], s0=g_ms[(size_t)i*48+tid*4+1];
    float m1=g_ms[(size_t)i*48+tid*4+2], s1=g_ms[(size_t)i*48+tid*4+3];
    float m=fmaxf(m0,m1);
    float f0=__expf(m0-m), f1=__expf(m1-m);
    float inv=1.f/(s0*f0+s1*f1);
    ff[tid][0]=f0*inv; ff[tid][1]=f1*inv;
    g_fac[i*24+tid*2+0]=f0*inv; g_fac[i*24+tid*2+1]=f1*inv;
  }
  __syncthreads();
  const float* p0=g_o2p + (size_t)i*2048;
  const float* p1=g_o2p + (size_t)(NNt+i)*2048;
  for(int l=tid;l<1536;l+=256){ int h=l>>7;
    g_feat[(size_t)i*2112 + l] = p0[l]*ff[h][0] + p1[l]*ff[h][1];
  }
}

// ---------------- out_global: coalesced scalar, 512 threads (8 dp-groups × 3) ----------------
__global__ void k_og(){
  __shared__ float Ws[64][129];
  __shared__ float Bsm[128][25];
  __shared__ float facs[64];
  int h=blockIdx.y, i0=blockIdx.x*64, tid=threadIdx.x;   // 512 threads
  int ii=tid&63, dg=(tid>>6)*3;
  float acc[3]={};
  for(int j0=0;j0<NNt;j0+=128){
    if(tid<64) facs[tid]=g_fac[(i0+tid)*24 + h*2 + (j0>=JH?1:0)];
    for(int l=tid;l<2048;l+=512){ int r=l>>5, c4=(l&31)*4;
      float4 v=*(const float4*)&g_W[((size_t)(i0+r)*Hh+h)*NNt + j0 + c4];
      Ws[r][c4]=v.x; Ws[r][c4+1]=v.y; Ws[r][c4+2]=v.z; Ws[r][c4+3]=v.w; }
    for(int l=tid;l<3072;l+=512){ int jj=l/24, dp=l%24;
      Bsm[jj][dp]=g_vph[((size_t)h*NNt+j0+jj)*24+dp]; }
    __syncthreads();
    float fi=facs[ii];
    float ts[3]={};
    #pragma unroll 4
    for(int jj=0;jj<128;jj++){
      float w=Ws[ii][jj];
      #pragma unroll
      for(int k=0;k<3;k++) ts[k]+=w*Bsm[jj][dg+k];
    }
    #pragma unroll
    for(int k=0;k<3;k++) acc[k]+=ts[k]*fi;
    __syncthreads();
  }
  for(int k=0;k<3;k++) g_og[((size_t)(i0+ii)*24+dg+k)*Hh+h]=acc[k];
}

// ---------------- frame invert + o_pt / o_norm / o_1d -> feat[1536:2112] ----------------
__global__ void k_asm(){
  int i=blockIdx.x, tid=threadIdx.x;         // 96 threads, (p,h)
  __shared__ float Rs[9], ts[3];
  if(tid<9) Rs[tid]=g_R[i*9+tid];
  if(tid<3) ts[tid]=g_t[i*3+tid];
  __syncthreads();
  int p=tid/12, h=tid%12;
  float o0=g_og[((size_t)i*24+ 0+p)*Hh+h]-ts[0];
  float o1=g_og[((size_t)i*24+ 8+p)*Hh+h]-ts[1];
  float o2=g_og[((size_t)i*24+16+p)*Hh+h]-ts[2];
  float* fbp=&g_feat[(size_t)i*2112];
  float n2=0.f;
  #pragma unroll
  for(int d=0;d<3;d++){
    float ol=Rs[0*3+d]*o0+Rs[1*3+d]*o1+Rs[2*3+d]*o2;   // R^T
    fbp[1728+(p*12+h)*3+d]=ol; n2+=ol*ol;
  }
  fbp[2016+p*12+h]=sqrtf(n2);
  for(int l=tid;l<192;l+=96) fbp[1536+l]=g_raw[(size_t)i*1152 + (l/16)*48+32+(l%16)];  // o_1d = v_1d
}

// ---------------- final GEMM (tf32 mma, split-K=4) ----------------
__global__ void k_final(const float* __restrict__ fw){
  __shared__ float As[16][72], Bs[16][72];
  int n0=blockIdx.x*64, m0=blockIdx.y*64, kslice=blockIdx.z, tid=threadIdx.x;
  int wid=tid>>5, lane=tid&31, g=lane>>2, tg=lane&3;
  int mw=(wid&3)*16, nw=(wid>>2)*32;
  float acc[4][4]={};
  for(int k0=kslice*528;k0<(kslice+1)*528;k0+=16){
    for(int l=tid;l<1024;l+=256){ int kk=l&15,mm=l>>4; As[kk][mm]=f2tff(g_feat[(size_t)(m0+mm)*2112+k0+kk]); }
    for(int l=tid;l<1024;l+=256){ int nn=l&63,kk=l>>6; Bs[kk][nn]=f2tff(fw[(size_t)(k0+kk)*C1c+n0+nn]); }
    __syncthreads();
    #pragma unroll
    for(int ks=0;ks<16;ks+=8){
      uint32_t a0=__float_as_uint(As[ks+tg  ][mw+g  ]);
      uint32_t a1=__float_as_uint(As[ks+tg  ][mw+g+8]);
      uint32_t a2=__float_as_uint(As[ks+tg+4][mw+g  ]);
      uint32_t a3=__float_as_uint(As[ks+tg+4][mw+g+8]);
      #pragma unroll
      for(int blk=0;blk<4;blk++){
        uint32_t b0=__float_as_uint(Bs[ks+tg  ][nw+blk*8+g]);
        uint32_t b1=__float_as_uint(Bs[ks+tg+4][nw+blk*8+g]);
        mma_tf32(acc[blk][0],acc[blk][1],acc[blk][2],acc[blk][3],a0,a1,a2,a3,b0,b1);
      }
    }
    __syncthreads();
  }
  #pragma unroll
  for(int blk=0;blk<4;blk++){
    int r0=m0+mw+g, c=n0+nw+blk*8+tg*2;
    g_fin[kslice][(size_t)r0*C1c+c]    =acc[blk][0];
    g_fin[kslice][(size_t)r0*C1c+c+1]  =acc[blk][1];
    g_fin[kslice][(size_t)(r0+8)*C1c+c]  =acc[blk][2];
    g_fin[kslice][(size_t)(r0+8)*C1c+c+1]=acc[blk][3];
  }
}

__global__ void k_comb(const float* __restrict__ fbias, float* __restrict__ out){
  int idx=blockIdx.x*256+threadIdx.x;
  if(idx<NNt*C1c)
    out[idx]=g_fin[0][idx]+g_fin[1][idx]+g_fin[2][idx]+g_fin[3][idx]+fbias[idx%C1c];
}

extern "C" void kernel_launch(void* const* d_in, const int* in_sizes, int n_in,
                              void* d_out, int out_size){
  const float* rec1d=(const float*)d_in[0];
  const float* lig1d=(const float*)d_in[1];
  const float* rep  =(const float*)d_in[2];
  const float* recT =(const float*)d_in[3];
  const float* ligT =(const float*)d_in[4];
  const float* rw1  =(const float*)d_in[5];
  const float* rwp  =(const float*)d_in[6];
  const float* lw1  =(const float*)d_in[7];
  const float* lwp  =(const float*)d_in[8];
  const float* rrw  =(const float*)d_in[9];
  const float* llw  =(const float*)d_in[10];
  const float* rlw  =(const float*)d_in[11];
  const float* lrw  =(const float*)d_in[12];
  const float* fw   =(const float*)d_in[13];
  const float* fbias=(const float*)d_in[14];
  float* out=(float*)d_out;

  static int smem_set = 0;
  int att_smem = (12*WP2 + 2*64*PADc + 2*128*WQP + 16*PP2 + 48 + 12*68) * 4;
  if(!smem_set){
    cudaFuncSetAttribute(k_att, cudaFuncAttributeMaxDynamicSharedMemorySize, att_smem);
    smem_set = 1;
  }

  k_proj   <<<dim3(18,12),256>>>(rec1d,lig1d,rw1,rwp,lw1,lwp);
  k_frame  <<<768,192>>>(recT,ligT);
  k_qk     <<<dim3(12,12,12),256>>>();
  k_att    <<<dim3(2,768),512,att_smem>>>(rep,rrw,llw,rlw,lrw);
  k_comb2  <<<768,256>>>();
  k_og     <<<dim3(12,12),512>>>();
  k_asm    <<<768,96>>>();
  k_final  <<<dim3(6,12,4),256>>>(fw);
  k_comb   <<<1152,256>>>(fbias,out);
}

// round 14
// speedup vs baseline: 1.1881x; 1.1881x over previous
#include <cuda_runtime.h>
#include <math.h>
#include <stdint.h>

#define Hh 12
#define NRr 512
#define NNt 768
#define C1c 384
#define C2c 128
#define WC_ 0.23570226039551584f   /* sqrt(1/18) */
#define WLS 0.14433756729740643f   /* sqrt(1/3)/4 */

#define JH   384                   /* j per half (per k_att CTA) */
#define TJ   64                    /* j rows per tile */
#define WP2  392                   /* Wt row pad */
#define PADc 132                   /* rep tile row pad */
#define WQP  16                    /* wq row pad */
#define PP2  68                    /* psm row pad */

static __device__ float g_raw[(size_t)NNt*1152];
static __device__ float g_R[NNt*9];
static __device__ float g_t[NNt*3];
static __device__ float g_q[(size_t)NNt*Hh*32];
static __device__ float g_kT[(size_t)Hh*32*NNt];
static __device__ float g_vph[(size_t)Hh*NNt*24];
static __device__ float g_W[(size_t)NNt*Hh*NNt];
static __device__ float g_ogp[2][(size_t)NNt*24*Hh];
static __device__ float g_feat[(size_t)NNt*2112];
static __device__ float g_fin[8][(size_t)NNt*C1c];
static __device__ float g_o2p[(size_t)2*NNt*2048];
static __device__ float g_ms[NNt*48];
static __device__ float g_fac[NNt*24];

__device__ __forceinline__ void cp16(float* dst, const float* src){
  unsigned sa=(unsigned)__cvta_generic_to_shared(dst);
  asm volatile("cp.async.cg.shared.global [%0], [%1], 16;\n" :: "r"(sa), "l"(src));
}
__device__ __forceinline__ uint32_t f2tf(float x){
  uint32_t r; asm("cvt.rna.tf32.f32 %0, %1;\n" : "=r"(r) : "f"(x)); return r;
}
__device__ __forceinline__ float f2tff(float x){
  uint32_t r; asm("cvt.rna.tf32.f32 %0, %1;\n" : "=r"(r) : "f"(x)); return __uint_as_float(r);
}
__device__ __forceinline__ void mma_tf32(float& d0,float& d1,float& d2,float& d3,
    uint32_t a0,uint32_t a1,uint32_t a2,uint32_t a3,uint32_t b0,uint32_t b1){
  asm volatile("mma.sync.aligned.m16n8k8.row.col.f32.tf32.tf32.f32 "
    "{%0,%1,%2,%3},{%4,%5,%6,%7},{%8,%9},{%0,%1,%2,%3};\n"
    : "+f"(d0),"+f"(d1),"+f"(d2),"+f"(d3)
    : "r"(a0),"r"(a1),"r"(a2),"r"(a3),"r"(b0),"r"(b1));
}

// ---------------- projections (tf32 mma): raw[768][1152] = X @ W ----------------
__global__ void k_proj(const float* __restrict__ rec1d, const float* __restrict__ lig1d,
                       const float* __restrict__ rw1, const float* __restrict__ rwp,
                       const float* __restrict__ lw1, const float* __restrict__ lwp){
  __shared__ float As[16][72], Bs[16][72];
  int m0=blockIdx.y*64, n0=blockIdx.x*64, tid=threadIdx.x;
  int wid=tid>>5, lane=tid&31, g=lane>>2, tg=lane&3;
  int mw=(wid&3)*16, nw=(wid>>2)*32;
  const float* X  = (m0<NRr)? rec1d+(size_t)m0*C1c : lig1d+(size_t)(m0-NRr)*C1c;
  const float* Bm = (m0<NRr)? ((n0<576)? rw1: rwp) : ((n0<576)? lw1: lwp);
  int nb = (n0<576)? n0 : n0-576;
  float acc[4][4]={};
  for(int k0=0;k0<C1c;k0+=16){
    for(int l=tid;l<1024;l+=256){ int kk=l&15,mm=l>>4; As[kk][mm]=f2tff(X[(size_t)mm*C1c+k0+kk]); }
    for(int l=tid;l<1024;l+=256){ int nn=l&63,kk=l>>6; Bs[kk][nn]=f2tff(Bm[(size_t)(k0+kk)*576+nb+nn]); }
    __syncthreads();
    #pragma unroll
    for(int ks=0;ks<16;ks+=8){
      uint32_t a0=__float_as_uint(As[ks+tg  ][mw+g  ]);
      uint32_t a1=__float_as_uint(As[ks+tg  ][mw+g+8]);
      uint32_t a2=__float_as_uint(As[ks+tg+4][mw+g  ]);
      uint32_t a3=__float_as_uint(As[ks+tg+4][mw+g+8]);
      #pragma unroll
      for(int blk=0;blk<4;blk++){
        uint32_t b0=__float_as_uint(Bs[ks+tg  ][nw+blk*8+g]);
        uint32_t b1=__float_as_uint(Bs[ks+tg+4][nw+blk*8+g]);
        mma_tf32(acc[blk][0],acc[blk][1],acc[blk][2],acc[blk][3],a0,a1,a2,a3,b0,b1);
      }
    }
    __syncthreads();
  }
  #pragma unroll
  for(int blk=0;blk<4;blk++){
    int r0=m0+mw+g, c=n0+nw+blk*8+tg*2;
    g_raw[(size_t)r0*1152+c]    =acc[blk][0];
    g_raw[(size_t)r0*1152+c+1]  =acc[blk][1];
    g_raw[(size_t)(r0+8)*1152+c]  =acc[blk][2];
    g_raw[(size_t)(r0+8)*1152+c+1]=acc[blk][3];
  }
}

// ---------------- frames: R,t, point transform, build q/k vectors & vph ----------------
__global__ void k_frame(const float* __restrict__ recT, const float* __restrict__ ligT){
  int i=blockIdx.x, d=threadIdx.x;           // 192 threads, d = h*16+e
  __shared__ float k2p[12][4];
  const float* T=(i<NRr)? recT+(size_t)i*7 : ligT+(size_t)(i-NRr)*7;
  float qw=T[0],qx=T[1],qy=T[2],qz=T[3];
  float inr=rsqrtf(qw*qw+qx*qx+qy*qy+qz*qz);
  qw*=inr;qx*=inr;qy*=inr;qz*=inr;
  float R[9];
  R[0]=1.f-2.f*(qy*qy+qz*qz); R[1]=2.f*(qx*qy-qw*qz); R[2]=2.f*(qx*qz+qw*qy);
  R[3]=2.f*(qx*qy+qw*qz); R[4]=1.f-2.f*(qx*qx+qz*qz); R[5]=2.f*(qy*qz-qw*qx);
  R[6]=2.f*(qx*qz-qw*qy); R[7]=2.f*(qy*qz+qw*qx); R[8]=1.f-2.f*(qx*qx+qy*qy);
  float t0=T[4],t1=T[5],t2=T[6];
  if(d<9) g_R[i*9+d]=R[d];
  if(d<3) g_t[i*3+d]=(d==0?t0:(d==1?t1:t2));
  const float* rp=g_raw+(size_t)i*1152+576;
  float l0=rp[d], l1=rp[192+d], l2=rp[384+d];
  float g0=R[0]*l0+R[1]*l1+R[2]*l2+t0;
  float g1=R[3]*l0+R[4]*l1+R[5]*l2+t1;
  float g2=R[6]*l0+R[7]*l1+R[8]*l2+t2;
  int h=d>>4, e=d&15;
  if(e<4){                                   // k-points
    k2p[h][e]=g0*g0+g1*g1+g2*g2;
    g_kT[(size_t)(h*32+0+e)*NNt+i]=g0;
    g_kT[(size_t)(h*32+4+e)*NNt+i]=g1;
    g_kT[(size_t)(h*32+8+e)*NNt+i]=g2;
  } else if(e<8){                            // q-points (pre-scaled)
    int p=e-4;
    float* q=&g_q[((size_t)i*Hh+h)*32];
    q[0+p]=2.f*WC_*g0; q[4+p]=2.f*WC_*g1; q[8+p]=2.f*WC_*g2;
  } else {                                   // v-points
    int p=e-8;
    float* v=&g_vph[((size_t)h*NNt+i)*24];
    v[p]=g0; v[8+p]=g1; v[16+p]=g2;
  }
  __syncthreads();
  const float* r1=g_raw+(size_t)i*1152;
  int s=e;
  g_kT[(size_t)(h*32+12+s)*NNt+i]=r1[h*48+s];            // k1
  g_q[((size_t)i*Hh+h)*32+12+s]=WLS*r1[h*48+16+s];       // q1 (pre-scaled)
  if(s==0){
    float K2=k2p[h][0]+k2p[h][1]+k2p[h][2]+k2p[h][3];
    g_kT[(size_t)(h*32+28)*NNt+i]=-WC_*K2;
    g_q[((size_t)i*Hh+h)*32+28]=1.f;
  } else if(s<4){
    g_kT[(size_t)(h*32+28+s)*NNt+i]=0.f;
    g_q[((size_t)i*Hh+h)*32+28+s]=0.f;
  }
}

// ------- qk logits (tf32 mma, hi/lo compensated) + coalesced smem-staged store -------
__global__ void k_qk(){
  __shared__ float qsm[4*2304];              // Ahi|Alo|Bhi|Blo, reused as store tile
  float* Ahi=qsm; float* Alo=qsm+2304; float* Bhi=qsm+4608; float* Blo=qsm+6912;
  int j0=blockIdx.x*64, i0=blockIdx.y*64, h=blockIdx.z, tid=threadIdx.x;
  int wid=tid>>5, lane=tid&31, g=lane>>2, tg=lane&3;
  int mw=(wid&3)*16, nw=(wid>>2)*32;
  for(int l=tid;l<2048;l+=256){ int kk=l&31, mm=l>>5;
    float v=g_q[((size_t)(i0+mm)*Hh+h)*32+kk];
    float hi=f2tff(v);
    Ahi[kk*72+mm]=hi; Alo[kk*72+mm]=f2tff(v-hi); }
  for(int l=tid;l<2048;l+=256){ int kk=l>>6, nn=l&63;
    float v=g_kT[(size_t)(h*32+kk)*NNt + j0+nn];
    float hi=f2tff(v);
    Bhi[kk*72+nn]=hi; Blo[kk*72+nn]=f2tff(v-hi); }
  __syncthreads();
  float acc[4][4]={};
  #pragma unroll
  for(int ks=0;ks<32;ks+=8){
    uint32_t ah0=__float_as_uint(Ahi[(ks+tg  )*72+mw+g  ]);
    uint32_t ah1=__float_as_uint(Ahi[(ks+tg  )*72+mw+g+8]);
    uint32_t ah2=__float_as_uint(Ahi[(ks+tg+4)*72+mw+g  ]);
    uint32_t ah3=__float_as_uint(Ahi[(ks+tg+4)*72+mw+g+8]);
    uint32_t al0=__float_as_uint(Alo[(ks+tg  )*72+mw+g  ]);
    uint32_t al1=__float_as_uint(Alo[(ks+tg  )*72+mw+g+8]);
    uint32_t al2=__float_as_uint(Alo[(ks+tg+4)*72+mw+g  ]);
    uint32_t al3=__float_as_uint(Alo[(ks+tg+4)*72+mw+g+8]);
    #pragma unroll
    for(int blk=0;blk<4;blk++){
      uint32_t bh0=__float_as_uint(Bhi[(ks+tg  )*72+nw+blk*8+g]);
      uint32_t bh1=__float_as_uint(Bhi[(ks+tg+4)*72+nw+blk*8+g]);
      uint32_t bl0=__float_as_uint(Blo[(ks+tg  )*72+nw+blk*8+g]);
      uint32_t bl1=__float_as_uint(Blo[(ks+tg+4)*72+nw+blk*8+g]);
      mma_tf32(acc[blk][0],acc[blk][1],acc[blk][2],acc[blk][3],ah0,ah1,ah2,ah3,bl0,bl1);
      mma_tf32(acc[blk][0],acc[blk][1],acc[blk][2],acc[blk][3],al0,al1,al2,al3,bh0,bh1);
      mma_tf32(acc[blk][0],acc[blk][1],acc[blk][2],acc[blk][3],ah0,ah1,ah2,ah3,bh0,bh1);
    }
  }
  __syncthreads();                            // all fragment reads done; reuse qsm
  float* S=qsm;                               // [64][65]
  #pragma unroll
  for(int blk=0;blk<4;blk++){
    int r0=mw+g, c=nw+blk*8+tg*2;
    S[r0*65+c]    =acc[blk][0]; S[r0*65+c+1]    =acc[blk][1];
    S[(r0+8)*65+c]=acc[blk][2]; S[(r0+8)*65+c+1]=acc[blk][3];
  }
  __syncthreads();
  for(int l=tid;l<1024;l+=256){ int r=l>>4, c4=(l&15)*4;
    float4 v=make_float4(S[r*65+c4],S[r*65+c4+1],S[r*65+c4+2],S[r*65+c4+3]);
    *(float4*)&g_W[((size_t)(i0+r)*Hh+h)*NNt + j0 + c4] = v;
  }
}

// ---- fused half-row attention: bias + partial online softmax + partial o_2d ----
// grid (2,768). 64-row tiles, double-buffered, 2 CTAs/SM, single-phase bias accum.
__global__ void __launch_bounds__(512,2) k_att(const float* __restrict__ rep,
                      const float* __restrict__ rr, const float* __restrict__ ll,
                      const float* __restrict__ rl, const float* __restrict__ lr){
  extern __shared__ float sm[];
  float* Wt   = sm;                        // [12][WP2]
  float* reps0= Wt + 12*WP2;               // [64][PADc]
  float* reps1= reps0 + 64*PADc;           // [64][PADc]
  float* wq   = reps1 + 64*PADc;           // [2][128][WQP]
  float* psm  = wq + 2*128*WQP;            // [16][PP2]
  float* ctrl = psm + 16*PP2;              // m[16], s[16], sc[16]
  float* sm_m = ctrl; float* sm_s = ctrl+16; float* sm_sc = ctrl+32;
  float* Wt2  = ctrl + 48;                 // [12][68] per-tile K-half-1 partials
  int half=blockIdx.x, i=blockIdx.y, tid=threadIdx.x;
  int jbase = half*JH;
  const float* wA = (i<NRr)? rr : lr;      // j < 512
  const float* wB = (i<NRr)? rl : ll;      // j >= 512
  // prologue: prefetch tiles 0 and 1
  {
    const float* rb = rep + ((size_t)i*NNt + jbase)*C2c;
    #pragma unroll
    for(int k=0;k<4;k++){ int l=tid+512*k; int jj=l>>5, c4=(l&31)*4;
      cp16(&reps0[jj*PADc+c4], rb + (size_t)jj*C2c + c4); }
    asm volatile("cp.async.commit_group;\n");
    rb += (size_t)TJ*C2c;
    #pragma unroll
    for(int k=0;k<4;k++){ int l=tid+512*k; int jj=l>>5, c4=(l&31)*4;
      cp16(&reps1[jj*PADc+c4], rb + (size_t)jj*C2c + c4); }
    asm volatile("cp.async.commit_group;\n");
  }
  if(tid<16){ sm_m[tid]=(tid<12)?-1e30f:0.f; sm_s[tid]=(tid<12)?0.f:1.f; sm_sc[tid]=1.f; }
  for(int l=tid;l<2*128*WQP;l+=512){
    int q=l/(128*WQP), rem=l%(128*WQP), c=rem/WQP, h=rem%WQP;
    float v = (h<12)? ((q==0)? wA[c*12+h] : wB[c*12+h]) : 0.f;
    wq[l]=__uint_as_float(f2tf(v));
  }
  for(int l=tid;l<16*PP2;l+=512) psm[l]=0.f;
  for(int l=tid;l<1152;l+=512){ int h=l/96, j4=(l%96)*4;
    *(float4*)&Wt[h*WP2+j4] = *(const float4*)&g_W[((size_t)i*Hh+h)*NNt + jbase + j4]; }

  int wid=tid>>5, lane=tid&31, g=lane>>2, tg=lane&3;
  int m0=(wid&3)*16, n0=((wid>>2)&1)*8, kb=(wid>>3)*64;   // bias mapping (K split)
  int cb0=wid*8;                                          // o2d mapping
  float o0=0.f,o1=0.f,o2=0.f,o3=0.f;

  for(int t=0;t<6;t++){
    float* rp = (t&1)? reps1 : reps0;
    if(t<5) asm volatile("cp.async.wait_group 1;\n");
    else    asm volatile("cp.async.wait_group 0;\n");
    __syncthreads();
    // ---- bias mma: K-half 0 adds into Wt, K-half 1 writes Wt2 (no serialization) ----
    {
      const float* wqs = wq + ((jbase + t*TJ >= NRr)? 128*WQP : 0);
      float c0=0.f,c1=0.f,c2=0.f,c3=0.f;
      #pragma unroll
      for(int k=0;k<8;k++){
        int k0=kb+k*8;
        uint32_t a0=__float_as_uint(rp[(m0+g  )*PADc + k0+tg  ]);
        uint32_t a1=__float_as_uint(rp[(m0+g+8)*PADc + k0+tg  ]);
        uint32_t a2=__float_as_uint(rp[(m0+g  )*PADc + k0+tg+4]);
        uint32_t a3=__float_as_uint(rp[(m0+g+8)*PADc + k0+tg+4]);
        uint32_t b0=__float_as_uint(wqs[(k0+tg  )*WQP + n0+g]);
        uint32_t b1=__float_as_uint(wqs[(k0+tg+4)*WQP + n0+g]);
        mma_tf32(c0,c1,c2,c3,a0,a1,a2,a3,b0,b1);
      }
      int h0=n0+tg*2, h1=h0+1, j0l=m0+g, j1l=m0+g+8;
      if(wid<8){
        if(h0<12){ Wt[h0*WP2+t*TJ+j0l]+=c0; Wt[h0*WP2+t*TJ+j1l]+=c2; }
        if(h1<12){ Wt[h1*WP2+t*TJ+j0l]+=c1; Wt[h1*WP2+t*TJ+j1l]+=c3; }
      } else {
        if(h0<12){ Wt2[h0*68+j0l]=c0; Wt2[h0*68+j1l]=c2; }
        if(h1<12){ Wt2[h1*68+j0l]=c1; Wt2[h1*68+j1l]=c3; }
      }
    }
    __syncthreads();
    // ---- online softmax (warp per head, 64 cols): merge Wt+Wt2, write back ----
    if(wid<12){
      float v[2]; float tmax=-1e30f;
      #pragma unroll
      for(int k=0;k<2;k++){
        v[k]=Wt[wid*WP2+t*TJ+lane+32*k]+Wt2[wid*68+lane+32*k];
        Wt[wid*WP2+t*TJ+lane+32*k]=v[k];
        tmax=fmaxf(tmax,v[k]); }
      #pragma unroll
      for(int o=16;o;o>>=1) tmax=fmaxf(tmax,__shfl_xor_sync(0xffffffffu,tmax,o));
      float mold=sm_m[wid], mnew=fmaxf(mold,tmax);
      float ps=0.f;
      #pragma unroll
      for(int k=0;k<2;k++){ float p=__expf(v[k]-mnew);
        psm[wid*PP2+lane+32*k]=__uint_as_float(f2tf(p)); ps+=p; }
      #pragma unroll
      for(int o=16;o;o>>=1) ps+=__shfl_xor_sync(0xffffffffu,ps,o);
      if(lane==0){ float sc=__expf(mold-mnew); sm_sc[wid]=sc; sm_m[wid]=mnew; sm_s[wid]=sm_s[wid]*sc+ps; }
    }
    __syncthreads();
    // ---- o2d mma: rescale then accumulate (K=64) ----
    {
      float s_lo=sm_sc[g], s_hi=sm_sc[g+8];
      o0*=s_lo; o1*=s_lo; o2*=s_hi; o3*=s_hi;
      #pragma unroll
      for(int k=0;k<8;k++){
        int k0=k*8;
        uint32_t a0=__float_as_uint(psm[(g  )*PP2 + k0+tg  ]);
        uint32_t a1=__float_as_uint(psm[(g+8)*PP2 + k0+tg  ]);
        uint32_t a2=__float_as_uint(psm[(g  )*PP2 + k0+tg+4]);
        uint32_t a3=__float_as_uint(psm[(g+8)*PP2 + k0+tg+4]);
        uint32_t b0=__float_as_uint(rp[(k0+tg  )*PADc + cb0+g]);
        uint32_t b1=__float_as_uint(rp[(k0+tg+4)*PADc + cb0+g]);
        mma_tf32(o0,o1,o2,o3,a0,a1,a2,a3,b0,b1);
      }
    }
    __syncthreads();
    // ---- prefetch tile t+2 into this tile's (now free) buffer ----
    if(t<4){
      const float* rb = rep + ((size_t)i*NNt + jbase + (t+2)*TJ)*C2c;
      #pragma unroll
      for(int k=0;k<4;k++){ int l=tid+512*k; int jj=l>>5, c4=(l&31)*4;
        cp16(&rp[jj*PADc+c4], rb + (size_t)jj*C2c + c4); }
      asm volatile("cp.async.commit_group;\n");
    }
  }
  // ---- partial outputs ----
  if(tid<12){
    g_ms[(size_t)i*48 + tid*4 + half*2 + 0]=sm_m[tid];
    g_ms[(size_t)i*48 + tid*4 + half*2 + 1]=sm_s[tid];
  }
  {
    int cc=cb0+tg*2;
    float* ob = g_o2p + ((size_t)(half*NNt+i))*2048;
    ob[g*128+cc]=o0; ob[g*128+cc+1]=o1;
    ob[(g+8)*128+cc]=o2; ob[(g+8)*128+cc+1]=o3;
  }
  for(int l=tid;l<4608;l+=512){ int h=l/JH, jl=l-h*JH;
    g_W[((size_t)i*Hh+h)*NNt + jbase + jl] = __expf(Wt[h*WP2+jl]-sm_m[h]);
  }
}

// ---- combine halves: softmax factors + final o_2d -> g_feat[0:1536], g_fac ----
__global__ void k_comb2(){
  int i=blockIdx.x, tid=threadIdx.x;      // 256 threads
  __shared__ float ff[12][2];
  if(tid<12){
    float m0=g_ms[(size_t)i*48+tid*4+0], s0=g_ms[(size_t)i*48+tid*4+1];
    float m1=g_ms[(size_t)i*48+tid*4+2], s1=g_ms[(size_t)i*48+tid*4+3];
    float m=fmaxf(m0,m1);
    float f0=__expf(m0-m), f1=__expf(m1-m);
    float inv=1.f/(s0*f0+s1*f1);
    ff[tid][0]=f0*inv; ff[tid][1]=f1*inv;
    g_fac[i*24+tid*2+0]=f0*inv; g_fac[i*24+tid*2+1]=f1*inv;
  }
  __syncthreads();
  const float* p0=g_o2p + (size_t)i*2048;
  const float* p1=g_o2p + (size_t)(NNt+i)*2048;
  for(int l=tid;l<1536;l+=256){ int h=l>>7;
    g_feat[(size_t)i*2112 + l] = p0[l]*ff[h][0] + p1[l]*ff[h][1];
  }
}

// ---- out_global: coalesced scalar, j-half split (grid 12×12×2), 256 threads ----
__global__ void k_og(){
  __shared__ float Ws[64][129];
  __shared__ float Bsm[128][25];
  __shared__ float facs[64];
  int h=blockIdx.y, i0=blockIdx.x*64, half=blockIdx.z, tid=threadIdx.x;
  int ii=tid&63, dg=(tid>>6)*6;
  if(tid<64) facs[tid]=g_fac[(i0+tid)*24 + h*2 + half];
  float acc[6]={};
  for(int jt=0;jt<3;jt++){
    int j0=half*JH + jt*128;
    for(int l=tid;l<2048;l+=256){ int r=l>>5, c4=(l&31)*4;
      float4 v=*(const float4*)&g_W[((size_t)(i0+r)*Hh+h)*NNt + j0 + c4];
      Ws[r][c4]=v.x; Ws[r][c4+1]=v.y; Ws[r][c4+2]=v.z; Ws[r][c4+3]=v.w; }
    for(int l=tid;l<3072;l+=256){ int jj=l/24, dp=l%24;
      Bsm[jj][dp]=g_vph[((size_t)h*NNt+j0+jj)*24+dp]; }
    __syncthreads();
    #pragma unroll 4
    for(int jj=0;jj<128;jj++){
      float w=Ws[ii][jj];
      #pragma unroll
      for(int k=0;k<6;k++) acc[k]+=w*Bsm[jj][dg+k];
    }
    __syncthreads();
  }
  float fi=facs[ii];
  for(int k=0;k<6;k++) g_ogp[half][((size_t)(i0+ii)*24+dg+k)*Hh+h]=acc[k]*fi;
}

// ---------------- frame invert + o_pt / o_norm / o_1d -> feat[1536:2112] ----------------
__global__ void k_asm(){
  int i=blockIdx.x, tid=threadIdx.x;         // 96 threads, (p,h)
  __shared__ float Rs[9], ts[3];
  if(tid<9) Rs[tid]=g_R[i*9+tid];
  if(tid<3) ts[tid]=g_t[i*3+tid];
  __syncthreads();
  int p=tid/12, h=tid%12;
  float o0=g_ogp[0][((size_t)i*24+ 0+p)*Hh+h]+g_ogp[1][((size_t)i*24+ 0+p)*Hh+h]-ts[0];
  float o1=g_ogp[0][((size_t)i*24+ 8+p)*Hh+h]+g_ogp[1][((size_t)i*24+ 8+p)*Hh+h]-ts[1];
  float o2=g_ogp[0][((size_t)i*24+16+p)*Hh+h]+g_ogp[1][((size_t)i*24+16+p)*Hh+h]-ts[2];
  float* fbp=&g_feat[(size_t)i*2112];
  float n2=0.f;
  #pragma unroll
  for(int d=0;d<3;d++){
    float ol=Rs[0*3+d]*o0+Rs[1*3+d]*o1+Rs[2*3+d]*o2;   // R^T
    fbp[1728+(p*12+h)*3+d]=ol; n2+=ol*ol;
  }
  fbp[2016+p*12+h]=sqrtf(n2);
  for(int l=tid;l<192;l+=96) fbp[1536+l]=g_raw[(size_t)i*1152 + (l/16)*48+32+(l%16)];  // o_1d = v_1d
}

// ---------------- final GEMM (tf32 mma, split-K=8) ----------------
__global__ void k_final(const float* __restrict__ fw){
  __shared__ float As[16][72], Bs[16][72];
  int n0=blockIdx.x*64, m0=blockIdx.y*64, kslice=blockIdx.z, tid=threadIdx.x;
  int wid=tid>>5, lane=tid&31, g=lane>>2, tg=lane&3;
  int mw=(wid&3)*16, nw=(wid>>2)*32;
  int kbeg=kslice*272, kend=(kbeg+272<2112)? kbeg+272 : 2112;
  float acc[4][4]={};
  for(int k0=kbeg;k0<kend;k0+=16){
    for(int l=tid;l<1024;l+=256){ int kk=l&15,mm=l>>4; As[kk][mm]=f2tff(g_feat[(size_t)(m0+mm)*2112+k0+kk]); }
    for(int l=tid;l<1024;l+=256){ int nn=l&63,kk=l>>6; Bs[kk][nn]=f2tff(fw[(size_t)(k0+kk)*C1c+n0+nn]); }
    __syncthreads();
    #pragma unroll
    for(int ks=0;ks<16;ks+=8){
      uint32_t a0=__float_as_uint(As[ks+tg  ][mw+g  ]);
      uint32_t a1=__float_as_uint(As[ks+tg  ][mw+g+8]);
      uint32_t a2=__float_as_uint(As[ks+tg+4][mw+g  ]);
      uint32_t a3=__float_as_uint(As[ks+tg+4][mw+g+8]);
      #pragma unroll
      for(int blk=0;blk<4;blk++){
        uint32_t b0=__float_as_uint(Bs[ks+tg  ][nw+blk*8+g]);
        uint32_t b1=__float_as_uint(Bs[ks+tg+4][nw+blk*8+g]);
        mma_tf32(acc[blk][0],acc[blk][1],acc[blk][2],acc[blk][3],a0,a1,a2,a3,b0,b1);
      }
    }
    __syncthreads();
  }
  #pragma unroll
  for(int blk=0;blk<4;blk++){
    int r0=m0+mw+g, c=n0+nw+blk*8+tg*2;
    g_fin[kslice][(size_t)r0*C1c+c]    =acc[blk][0];
    g_fin[kslice][(size_t)r0*C1c+c+1]  =acc[blk][1];
    g_fin[kslice][(size_t)(r0+8)*C1c+c]  =acc[blk][2];
    g_fin[kslice][(size_t)(r0+8)*C1c+c+1]=acc[blk][3];
  }
}

__global__ void k_comb(const float* __restrict__ fbias, float* __restrict__ out){
  int idx=blockIdx.x*256+threadIdx.x;
  if(idx<NNt*C1c){
    float s=fbias[idx%C1c];
    #pragma unroll
    for(int k=0;k<8;k++) s+=g_fin[k][idx];
    out[idx]=s;
  }
}

extern "C" void kernel_launch(void* const* d_in, const int* in_sizes, int n_in,
                              void* d_out, int out_size){
  const float* rec1d=(const float*)d_in[0];
  const float* lig1d=(const float*)d_in[1];
  const float* rep  =(const float*)d_in[2];
  const float* recT =(const float*)d_in[3];
  const float* ligT =(const float*)d_in[4];
  const float* rw1  =(const float*)d_in[5];
  const float* rwp  =(const float*)d_in[6];
  const float* lw1  =(const float*)d_in[7];
  const float* lwp  =(const float*)d_in[8];
  const float* rrw  =(const float*)d_in[9];
  const float* llw  =(const float*)d_in[10];
  const float* rlw  =(const float*)d_in[11];
  const float* lrw  =(const float*)d_in[12];
  const float* fw   =(const float*)d_in[13];
  const float* fbias=(const float*)d_in[14];
  float* out=(float*)d_out;

  static int smem_set = 0;
  int att_smem = (12*WP2 + 2*64*PADc + 2*128*WQP + 16*PP2 + 48 + 12*68) * 4;
  if(!smem_set){
    cudaFuncSetAttribute(k_att, cudaFuncAttributeMaxDynamicSharedMemorySize, att_smem);
    smem_set = 1;
  }

  k_proj   <<<dim3(18,12),256>>>(rec1d,lig1d,rw1,rwp,lw1,lwp);
  k_frame  <<<768,192>>>(recT,ligT);
  k_qk     <<<dim3(12,12,12),256>>>();
  k_att    <<<dim3(2,768),512,att_smem>>>(rep,rrw,llw,rlw,lrw);
  k_comb2  <<<768,256>>>();
  k_og     <<<dim3(12,12,2),256>>>();
  k_asm    <<<768,96>>>();
  k_final  <<<dim3(6,12,8),256>>>(fw);
  k_comb   <<<1152,256>>>(fbias,out);
}

// round 15
// speedup vs baseline: 1.3252x; 1.1154x over previous
#include <cuda_runtime.h>
#include <math.h>
#include <stdint.h>

#define Hh 12
#define NRr 512
#define NNt 768
#define C1c 384
#define C2c 128
#define WC_ 0.23570226039551584f   /* sqrt(1/18) */
#define WLS 0.14433756729740643f   /* sqrt(1/3)/4 */

#define JH   384                   /* j per half (per k_att CTA) */
#define TJ   64                    /* j rows per tile */
#define WP2  392                   /* Wt row pad */
#define PADc 132                   /* rep tile row pad */
#define WQP  16                    /* wq row pad */
#define PP2  68                    /* psm row pad */

static __device__ float g_raw[(size_t)NNt*1152];
static __device__ float g_raw2[(size_t)NNt*1152];
static __device__ float g_R[NNt*9];
static __device__ float g_t[NNt*3];
static __device__ float g_q[(size_t)NNt*Hh*32];
static __device__ float g_kT[(size_t)Hh*32*NNt];
static __device__ float g_vph[(size_t)Hh*NNt*24];
static __device__ float g_W[(size_t)NNt*Hh*NNt];
static __device__ float g_ogp[2][(size_t)NNt*24*Hh];
static __device__ float g_feat[(size_t)NNt*2112];
static __device__ float g_fin[8][(size_t)NNt*C1c];
static __device__ float g_o2p[(size_t)2*NNt*2048];
static __device__ float g_ms[NNt*48];

__device__ __forceinline__ void cp16(float* dst, const float* src){
  unsigned sa=(unsigned)__cvta_generic_to_shared(dst);
  asm volatile("cp.async.cg.shared.global [%0], [%1], 16;\n" :: "r"(sa), "l"(src));
}
__device__ __forceinline__ uint32_t f2tf(float x){
  uint32_t r; asm("cvt.rna.tf32.f32 %0, %1;\n" : "=r"(r) : "f"(x)); return r;
}
__device__ __forceinline__ float f2tff(float x){
  uint32_t r; asm("cvt.rna.tf32.f32 %0, %1;\n" : "=r"(r) : "f"(x)); return __uint_as_float(r);
}
__device__ __forceinline__ void mma_tf32(float& d0,float& d1,float& d2,float& d3,
    uint32_t a0,uint32_t a1,uint32_t a2,uint32_t a3,uint32_t b0,uint32_t b1){
  asm volatile("mma.sync.aligned.m16n8k8.row.col.f32.tf32.tf32.f32 "
    "{%0,%1,%2,%3},{%4,%5,%6,%7},{%8,%9},{%0,%1,%2,%3};\n"
    : "+f"(d0),"+f"(d1),"+f"(d2),"+f"(d3)
    : "r"(a0),"r"(a1),"r"(a2),"r"(a3),"r"(b0),"r"(b1));
}

// ------------- projections (tf32 mma, split-K=2): raw[768][1152] = X @ W -------------
__global__ void k_proj(const float* __restrict__ rec1d, const float* __restrict__ lig1d,
                       const float* __restrict__ rw1, const float* __restrict__ rwp,
                       const float* __restrict__ lw1, const float* __restrict__ lwp){
  __shared__ float As[16][72], Bs[16][72];
  int m0=blockIdx.y*64, n0=blockIdx.x*64, kslice=blockIdx.z, tid=threadIdx.x;
  int wid=tid>>5, lane=tid&31, g=lane>>2, tg=lane&3;
  int mw=(wid&3)*16, nw=(wid>>2)*32;
  const float* X  = (m0<NRr)? rec1d+(size_t)m0*C1c : lig1d+(size_t)(m0-NRr)*C1c;
  const float* Bm = (m0<NRr)? ((n0<576)? rw1: rwp) : ((n0<576)? lw1: lwp);
  int nb = (n0<576)? n0 : n0-576;
  float* dst = kslice? g_raw2 : g_raw;
  float acc[4][4]={};
  for(int k0=kslice*192;k0<(kslice+1)*192;k0+=16){
    for(int l=tid;l<1024;l+=256){ int kk=l&15,mm=l>>4; As[kk][mm]=f2tff(X[(size_t)mm*C1c+k0+kk]); }
    for(int l=tid;l<1024;l+=256){ int nn=l&63,kk=l>>6; Bs[kk][nn]=f2tff(Bm[(size_t)(k0+kk)*576+nb+nn]); }
    __syncthreads();
    #pragma unroll
    for(int ks=0;ks<16;ks+=8){
      uint32_t a0=__float_as_uint(As[ks+tg  ][mw+g  ]);
      uint32_t a1=__float_as_uint(As[ks+tg  ][mw+g+8]);
      uint32_t a2=__float_as_uint(As[ks+tg+4][mw+g  ]);
      uint32_t a3=__float_as_uint(As[ks+tg+4][mw+g+8]);
      #pragma unroll
      for(int blk=0;blk<4;blk++){
        uint32_t b0=__float_as_uint(Bs[ks+tg  ][nw+blk*8+g]);
        uint32_t b1=__float_as_uint(Bs[ks+tg+4][nw+blk*8+g]);
        mma_tf32(acc[blk][0],acc[blk][1],acc[blk][2],acc[blk][3],a0,a1,a2,a3,b0,b1);
      }
    }
    __syncthreads();
  }
  #pragma unroll
  for(int blk=0;blk<4;blk++){
    int r0=m0+mw+g, c=n0+nw+blk*8+tg*2;
    dst[(size_t)r0*1152+c]    =acc[blk][0];
    dst[(size_t)r0*1152+c+1]  =acc[blk][1];
    dst[(size_t)(r0+8)*1152+c]  =acc[blk][2];
    dst[(size_t)(r0+8)*1152+c+1]=acc[blk][3];
  }
}

// ---------------- frames: R,t, point transform, build q/k vectors & vph ----------------
__global__ void k_frame(const float* __restrict__ recT, const float* __restrict__ ligT){
  int i=blockIdx.x, d=threadIdx.x;           // 192 threads, d = h*16+e
  __shared__ float k2p[12][4];
  const float* T=(i<NRr)? recT+(size_t)i*7 : ligT+(size_t)(i-NRr)*7;
  float qw=T[0],qx=T[1],qy=T[2],qz=T[3];
  float inr=rsqrtf(qw*qw+qx*qx+qy*qy+qz*qz);
  qw*=inr;qx*=inr;qy*=inr;qz*=inr;
  float R[9];
  R[0]=1.f-2.f*(qy*qy+qz*qz); R[1]=2.f*(qx*qy-qw*qz); R[2]=2.f*(qx*qz+qw*qy);
  R[3]=2.f*(qx*qy+qw*qz); R[4]=1.f-2.f*(qx*qx+qz*qz); R[5]=2.f*(qy*qz-qw*qx);
  R[6]=2.f*(qx*qz-qw*qy); R[7]=2.f*(qy*qz+qw*qx); R[8]=1.f-2.f*(qx*qx+qy*qy);
  float t0=T[4],t1=T[5],t2=T[6];
  if(d<9) g_R[i*9+d]=R[d];
  if(d<3) g_t[i*3+d]=(d==0?t0:(d==1?t1:t2));
  const float* rp =g_raw +(size_t)i*1152+576;
  const float* rp2=g_raw2+(size_t)i*1152+576;
  float l0=rp[d]+rp2[d], l1=rp[192+d]+rp2[192+d], l2=rp[384+d]+rp2[384+d];
  float g0=R[0]*l0+R[1]*l1+R[2]*l2+t0;
  float g1=R[3]*l0+R[4]*l1+R[5]*l2+t1;
  float g2=R[6]*l0+R[7]*l1+R[8]*l2+t2;
  int h=d>>4, e=d&15;
  if(e<4){                                   // k-points
    k2p[h][e]=g0*g0+g1*g1+g2*g2;
    g_kT[(size_t)(h*32+0+e)*NNt+i]=g0;
    g_kT[(size_t)(h*32+4+e)*NNt+i]=g1;
    g_kT[(size_t)(h*32+8+e)*NNt+i]=g2;
  } else if(e<8){                            // q-points (pre-scaled)
    int p=e-4;
    float* q=&g_q[((size_t)i*Hh+h)*32];
    q[0+p]=2.f*WC_*g0; q[4+p]=2.f*WC_*g1; q[8+p]=2.f*WC_*g2;
  } else {                                   // v-points
    int p=e-8;
    float* v=&g_vph[((size_t)h*NNt+i)*24];
    v[p]=g0; v[8+p]=g1; v[16+p]=g2;
  }
  __syncthreads();
  const float* r1 =g_raw +(size_t)i*1152;
  const float* r12=g_raw2+(size_t)i*1152;
  int s=e;
  g_kT[(size_t)(h*32+12+s)*NNt+i]=r1[h*48+s]+r12[h*48+s];           // k1
  g_q[((size_t)i*Hh+h)*32+12+s]=WLS*(r1[h*48+16+s]+r12[h*48+16+s]); // q1 (pre-scaled)
  if(s==0){
    float K2=k2p[h][0]+k2p[h][1]+k2p[h][2]+k2p[h][3];
    g_kT[(size_t)(h*32+28)*NNt+i]=-WC_*K2;
    g_q[((size_t)i*Hh+h)*32+28]=1.f;
  } else if(s<4){
    g_kT[(size_t)(h*32+28+s)*NNt+i]=0.f;
    g_q[((size_t)i*Hh+h)*32+28+s]=0.f;
  }
}

// ------- qk logits (tf32 mma, hi/lo compensated) + coalesced smem-staged store -------
__global__ void k_qk(){
  __shared__ float qsm[4*2304];              // Ahi|Alo|Bhi|Blo, reused as store tile
  float* Ahi=qsm; float* Alo=qsm+2304; float* Bhi=qsm+4608; float* Blo=qsm+6912;
  int j0=blockIdx.x*64, i0=blockIdx.y*64, h=blockIdx.z, tid=threadIdx.x;
  int wid=tid>>5, lane=tid&31, g=lane>>2, tg=lane&3;
  int mw=(wid&3)*16, nw=(wid>>2)*32;
  for(int l=tid;l<2048;l+=256){ int kk=l&31, mm=l>>5;
    float v=g_q[((size_t)(i0+mm)*Hh+h)*32+kk];
    float hi=f2tff(v);
    Ahi[kk*72+mm]=hi; Alo[kk*72+mm]=f2tff(v-hi); }
  for(int l=tid;l<2048;l+=256){ int kk=l>>6, nn=l&63;
    float v=g_kT[(size_t)(h*32+kk)*NNt + j0+nn];
    float hi=f2tff(v);
    Bhi[kk*72+nn]=hi; Blo[kk*72+nn]=f2tff(v-hi); }
  __syncthreads();
  float acc[4][4]={};
  #pragma unroll
  for(int ks=0;ks<32;ks+=8){
    uint32_t ah0=__float_as_uint(Ahi[(ks+tg  )*72+mw+g  ]);
    uint32_t ah1=__float_as_uint(Ahi[(ks+tg  )*72+mw+g+8]);
    uint32_t ah2=__float_as_uint(Ahi[(ks+tg+4)*72+mw+g  ]);
    uint32_t ah3=__float_as_uint(Ahi[(ks+tg+4)*72+mw+g+8]);
    uint32_t al0=__float_as_uint(Alo[(ks+tg  )*72+mw+g  ]);
    uint32_t al1=__float_as_uint(Alo[(ks+tg  )*72+mw+g+8]);
    uint32_t al2=__float_as_uint(Alo[(ks+tg+4)*72+mw+g  ]);
    uint32_t al3=__float_as_uint(Alo[(ks+tg+4)*72+mw+g+8]);
    #pragma unroll
    for(int blk=0;blk<4;blk++){
      uint32_t bh0=__float_as_uint(Bhi[(ks+tg  )*72+nw+blk*8+g]);
      uint32_t bh1=__float_as_uint(Bhi[(ks+tg+4)*72+nw+blk*8+g]);
      uint32_t bl0=__float_as_uint(Blo[(ks+tg  )*72+nw+blk*8+g]);
      uint32_t bl1=__float_as_uint(Blo[(ks+tg+4)*72+nw+blk*8+g]);
      mma_tf32(acc[blk][0],acc[blk][1],acc[blk][2],acc[blk][3],ah0,ah1,ah2,ah3,bl0,bl1);
      mma_tf32(acc[blk][0],acc[blk][1],acc[blk][2],acc[blk][3],al0,al1,al2,al3,bh0,bh1);
      mma_tf32(acc[blk][0],acc[blk][1],acc[blk][2],acc[blk][3],ah0,ah1,ah2,ah3,bh0,bh1);
    }
  }
  __syncthreads();                            // all fragment reads done; reuse qsm
  float* S=qsm;                               // [64][65]
  #pragma unroll
  for(int blk=0;blk<4;blk++){
    int r0=mw+g, c=nw+blk*8+tg*2;
    S[r0*65+c]    =acc[blk][0]; S[r0*65+c+1]    =acc[blk][1];
    S[(r0+8)*65+c]=acc[blk][2]; S[(r0+8)*65+c+1]=acc[blk][3];
  }
  __syncthreads();
  for(int l=tid;l<1024;l+=256){ int r=l>>4, c4=(l&15)*4;
    float4 v=make_float4(S[r*65+c4],S[r*65+c4+1],S[r*65+c4+2],S[r*65+c4+3]);
    *(float4*)&g_W[((size_t)(i0+r)*Hh+h)*NNt + j0 + c4] = v;
  }
}

// ---- fused half-row attention: bias + partial online softmax + partial o_2d ----
// grid (2,768). 64-row tiles, double-buffered, 2 CTAs/SM, single-phase bias accum.
__global__ void __launch_bounds__(512,2) k_att(const float* __restrict__ rep,
                      const float* __restrict__ rr, const float* __restrict__ ll,
                      const float* __restrict__ rl, const float* __restrict__ lr){
  extern __shared__ float sm[];
  float* Wt   = sm;                        // [12][WP2]
  float* reps0= Wt + 12*WP2;               // [64][PADc]
  float* reps1= reps0 + 64*PADc;           // [64][PADc]
  float* wq   = reps1 + 64*PADc;           // [2][128][WQP]
  float* psm  = wq + 2*128*WQP;            // [16][PP2]
  float* ctrl = psm + 16*PP2;              // m[16], s[16], sc[16]
  float* sm_m = ctrl; float* sm_s = ctrl+16; float* sm_sc = ctrl+32;
  float* Wt2  = ctrl + 48;                 // [12][68] per-tile K-half-1 partials
  int half=blockIdx.x, i=blockIdx.y, tid=threadIdx.x;
  int jbase = half*JH;
  const float* wA = (i<NRr)? rr : lr;      // j < 512
  const float* wB = (i<NRr)? rl : ll;      // j >= 512
  // prologue: prefetch tiles 0 and 1
  {
    const float* rb = rep + ((size_t)i*NNt + jbase)*C2c;
    #pragma unroll
    for(int k=0;k<4;k++){ int l=tid+512*k; int jj=l>>5, c4=(l&31)*4;
      cp16(&reps0[jj*PADc+c4], rb + (size_t)jj*C2c + c4); }
    asm volatile("cp.async.commit_group;\n");
    rb += (size_t)TJ*C2c;
    #pragma unroll
    for(int k=0;k<4;k++){ int l=tid+512*k; int jj=l>>5, c4=(l&31)*4;
      cp16(&reps1[jj*PADc+c4], rb + (size_t)jj*C2c + c4); }
    asm volatile("cp.async.commit_group;\n");
  }
  if(tid<16){ sm_m[tid]=(tid<12)?-1e30f:0.f; sm_s[tid]=(tid<12)?0.f:1.f; sm_sc[tid]=1.f; }
  for(int l=tid;l<2*128*WQP;l+=512){
    int q=l/(128*WQP), rem=l%(128*WQP), c=rem/WQP, h=rem%WQP;
    float v = (h<12)? ((q==0)? wA[c*12+h] : wB[c*12+h]) : 0.f;
    wq[l]=__uint_as_float(f2tf(v));
  }
  for(int l=tid;l<16*PP2;l+=512) psm[l]=0.f;
  for(int l=tid;l<1152;l+=512){ int h=l/96, j4=(l%96)*4;
    *(float4*)&Wt[h*WP2+j4] = *(const float4*)&g_W[((size_t)i*Hh+h)*NNt + jbase + j4]; }

  int wid=tid>>5, lane=tid&31, g=lane>>2, tg=lane&3;
  int m0=(wid&3)*16, n0=((wid>>2)&1)*8, kb=(wid>>3)*64;   // bias mapping (K split)
  int cb0=wid*8;                                          // o2d mapping
  float o0=0.f,o1=0.f,o2=0.f,o3=0.f;

  for(int t=0;t<6;t++){
    float* rp = (t&1)? reps1 : reps0;
    if(t<5) asm volatile("cp.async.wait_group 1;\n");
    else    asm volatile("cp.async.wait_group 0;\n");
    __syncthreads();
    // ---- bias mma: K-half 0 adds into Wt, K-half 1 writes Wt2 (no serialization) ----
    {
      const float* wqs = wq + ((jbase + t*TJ >= NRr)? 128*WQP : 0);
      float c0=0.f,c1=0.f,c2=0.f,c3=0.f;
      #pragma unroll
      for(int k=0;k<8;k++){
        int k0=kb+k*8;
        uint32_t a0=__float_as_uint(rp[(m0+g  )*PADc + k0+tg  ]);
        uint32_t a1=__float_as_uint(rp[(m0+g+8)*PADc + k0+tg  ]);
        uint32_t a2=__float_as_uint(rp[(m0+g  )*PADc + k0+tg+4]);
        uint32_t a3=__float_as_uint(rp[(m0+g+8)*PADc + k0+tg+4]);
        uint32_t b0=__float_as_uint(wqs[(k0+tg  )*WQP + n0+g]);
        uint32_t b1=__float_as_uint(wqs[(k0+tg+4)*WQP + n0+g]);
        mma_tf32(c0,c1,c2,c3,a0,a1,a2,a3,b0,b1);
      }
      int h0=n0+tg*2, h1=h0+1, j0l=m0+g, j1l=m0+g+8;
      if(wid<8){
        if(h0<12){ Wt[h0*WP2+t*TJ+j0l]+=c0; Wt[h0*WP2+t*TJ+j1l]+=c2; }
        if(h1<12){ Wt[h1*WP2+t*TJ+j0l]+=c1; Wt[h1*WP2+t*TJ+j1l]+=c3; }
      } else {
        if(h0<12){ Wt2[h0*68+j0l]=c0; Wt2[h0*68+j1l]=c2; }
        if(h1<12){ Wt2[h1*68+j0l]=c1; Wt2[h1*68+j1l]=c3; }
      }
    }
    __syncthreads();
    // ---- online softmax (warp per head, 64 cols): merge Wt+Wt2, write back ----
    if(wid<12){
      float v[2]; float tmax=-1e30f;
      #pragma unroll
      for(int k=0;k<2;k++){
        v[k]=Wt[wid*WP2+t*TJ+lane+32*k]+Wt2[wid*68+lane+32*k];
        Wt[wid*WP2+t*TJ+lane+32*k]=v[k];
        tmax=fmaxf(tmax,v[k]); }
      #pragma unroll
      for(int o=16;o;o>>=1) tmax=fmaxf(tmax,__shfl_xor_sync(0xffffffffu,tmax,o));
      float mold=sm_m[wid], mnew=fmaxf(mold,tmax);
      float ps=0.f;
      #pragma unroll
      for(int k=0;k<2;k++){ float p=__expf(v[k]-mnew);
        psm[wid*PP2+lane+32*k]=__uint_as_float(f2tf(p)); ps+=p; }
      #pragma unroll
      for(int o=16;o;o>>=1) ps+=__shfl_xor_sync(0xffffffffu,ps,o);
      if(lane==0){ float sc=__expf(mold-mnew); sm_sc[wid]=sc; sm_m[wid]=mnew; sm_s[wid]=sm_s[wid]*sc+ps; }
    }
    __syncthreads();
    // ---- o2d mma: rescale then accumulate (K=64) ----
    {
      float s_lo=sm_sc[g], s_hi=sm_sc[g+8];
      o0*=s_lo; o1*=s_lo; o2*=s_hi; o3*=s_hi;
      #pragma unroll
      for(int k=0;k<8;k++){
        int k0=k*8;
        uint32_t a0=__float_as_uint(psm[(g  )*PP2 + k0+tg  ]);
        uint32_t a1=__float_as_uint(psm[(g+8)*PP2 + k0+tg  ]);
        uint32_t a2=__float_as_uint(psm[(g  )*PP2 + k0+tg+4]);
        uint32_t a3=__float_as_uint(psm[(g+8)*PP2 + k0+tg+4]);
        uint32_t b0=__float_as_uint(rp[(k0+tg  )*PADc + cb0+g]);
        uint32_t b1=__float_as_uint(rp[(k0+tg+4)*PADc + cb0+g]);
        mma_tf32(o0,o1,o2,o3,a0,a1,a2,a3,b0,b1);
      }
    }
    __syncthreads();
    // ---- prefetch tile t+2 into this tile's (now free) buffer ----
    if(t<4){
      const float* rb = rep + ((size_t)i*NNt + jbase + (t+2)*TJ)*C2c;
      #pragma unroll
      for(int k=0;k<4;k++){ int l=tid+512*k; int jj=l>>5, c4=(l&31)*4;
        cp16(&rp[jj*PADc+c4], rb + (size_t)jj*C2c + c4); }
      asm volatile("cp.async.commit_group;\n");
    }
  }
  // ---- partial outputs ----
  if(tid<12){
    g_ms[(size_t)i*48 + tid*4 + half*2 + 0]=sm_m[tid];
    g_ms[(size_t)i*48 + tid*4 + half*2 + 1]=sm_s[tid];
  }
  {
    int cc=cb0+tg*2;
    float* ob = g_o2p + ((size_t)(half*NNt+i))*2048;
    ob[g*128+cc]=o0; ob[g*128+cc+1]=o1;
    ob[(g+8)*128+cc]=o2; ob[(g+8)*128+cc+1]=o3;
  }
  for(int l=tid;l<4608;l+=512){ int h=l/JH, jl=l-h*JH;
    g_W[((size_t)i*Hh+h)*NNt + jbase + jl] = __expf(Wt[h*WP2+jl]-sm_m[h]);
  }
}

// ---- out_global: coalesced scalar, j-half split (grid 12×12×2), local softmax factors ----
__global__ void k_og(){
  __shared__ float Ws[64][129];
  __shared__ float Bsm[128][25];
  __shared__ float facs[64];
  int h=blockIdx.y, i0=blockIdx.x*64, half=blockIdx.z, tid=threadIdx.x;
  int ii=tid&63, dg=(tid>>6)*6;
  if(tid<64){
    int i=i0+tid;
    float m0=g_ms[(size_t)i*48+h*4+0], s0=g_ms[(size_t)i*48+h*4+1];
    float m1=g_ms[(size_t)i*48+h*4+2], s1=g_ms[(size_t)i*48+h*4+3];
    float m=fmaxf(m0,m1);
    float f0=__expf(m0-m), f1=__expf(m1-m);
    float inv=1.f/(s0*f0+s1*f1);
    facs[tid]=(half? f1 : f0)*inv;
  }
  float acc[6]={};
  for(int jt=0;jt<3;jt++){
    int j0=half*JH + jt*128;
    for(int l=tid;l<2048;l+=256){ int r=l>>5, c4=(l&31)*4;
      float4 v=*(const float4*)&g_W[((size_t)(i0+r)*Hh+h)*NNt + j0 + c4];
      Ws[r][c4]=v.x; Ws[r][c4+1]=v.y; Ws[r][c4+2]=v.z; Ws[r][c4+3]=v.w; }
    for(int l=tid;l<3072;l+=256){ int jj=l/24, dp=l%24;
      Bsm[jj][dp]=g_vph[((size_t)h*NNt+j0+jj)*24+dp]; }
    __syncthreads();
    #pragma unroll 4
    for(int jj=0;jj<128;jj++){
      float w=Ws[ii][jj];
      #pragma unroll
      for(int k=0;k<6;k++) acc[k]+=w*Bsm[jj][dg+k];
    }
    __syncthreads();
  }
  float fi=facs[ii];
  for(int k=0;k<6;k++) g_ogp[half][((size_t)(i0+ii)*24+dg+k)*Hh+h]=acc[k]*fi;
}

// ---- frame invert + o_pt/o_norm/o_1d + o_2d merge -> feat (absorbs old k_comb2) ----
__global__ void k_asm(){
  int i=blockIdx.x, tid=threadIdx.x;         // 96 threads, (p,h)
  __shared__ float Rs[9], ts[3];
  __shared__ float ff[12][2];
  if(tid<9) Rs[tid]=g_R[i*9+tid];
  if(tid<3) ts[tid]=g_t[i*3+tid];
  if(tid>=32 && tid<44){
    int hh=tid-32;
    float m0=g_ms[(size_t)i*48+hh*4+0], s0=g_ms[(size_t)i*48+hh*4+1];
    float m1=g_ms[(size_t)i*48+hh*4+2], s1=g_ms[(size_t)i*48+hh*4+3];
    float m=fmaxf(m0,m1);
    float f0=__expf(m0-m), f1=__expf(m1-m);
    float inv=1.f/(s0*f0+s1*f1);
    ff[hh][0]=f0*inv; ff[hh][1]=f1*inv;
  }
  __syncthreads();
  float* fbp=&g_feat[(size_t)i*2112];
  // o_2d merge (was k_comb2)
  {
    const float* p0=g_o2p + (size_t)i*2048;
    const float* p1=g_o2p + (size_t)(NNt+i)*2048;
    for(int l=tid;l<1536;l+=96){ int h=l>>7;
      fbp[l] = p0[l]*ff[h][0] + p1[l]*ff[h][1]; }
  }
  int p=tid/12, h=tid%12;
  float o0=g_ogp[0][((size_t)i*24+ 0+p)*Hh+h]+g_ogp[1][((size_t)i*24+ 0+p)*Hh+h]-ts[0];
  float o1=g_ogp[0][((size_t)i*24+ 8+p)*Hh+h]+g_ogp[1][((size_t)i*24+ 8+p)*Hh+h]-ts[1];
  float o2=g_ogp[0][((size_t)i*24+16+p)*Hh+h]+g_ogp[1][((size_t)i*24+16+p)*Hh+h]-ts[2];
  float n2=0.f;
  #pragma unroll
  for(int d=0;d<3;d++){
    float ol=Rs[0*3+d]*o0+Rs[1*3+d]*o1+Rs[2*3+d]*o2;   // R^T
    fbp[1728+(p*12+h)*3+d]=ol; n2+=ol*ol;
  }
  fbp[2016+p*12+h]=sqrtf(n2);
  for(int l=tid;l<192;l+=96){
    size_t idx=(size_t)i*1152 + (l/16)*48+32+(l%16);
    fbp[1536+l]=g_raw[idx]+g_raw2[idx];      // o_1d = v_1d
  }
}

// ---------------- final GEMM (tf32 mma, split-K=8) ----------------
__global__ void k_final(const float* __restrict__ fw){
  __shared__ float As[16][72], Bs[16][72];
  int n0=blockIdx.x*64, m0=blockIdx.y*64, kslice=blockIdx.z, tid=threadIdx.x;
  int wid=tid>>5, lane=tid&31, g=lane>>2, tg=lane&3;
  int mw=(wid&3)*16, nw=(wid>>2)*32;
  int kbeg=kslice*272, kend=(kbeg+272<2112)? kbeg+272 : 2112;
  float acc[4][4]={};
  for(int k0=kbeg;k0<kend;k0+=16){
    for(int l=tid;l<1024;l+=256){ int kk=l&15,mm=l>>4; As[kk][mm]=f2tff(g_feat[(size_t)(m0+mm)*2112+k0+kk]); }
    for(int l=tid;l<1024;l+=256){ int nn=l&63,kk=l>>6; Bs[kk][nn]=f2tff(fw[(size_t)(k0+kk)*C1c+n0+nn]); }
    __syncthreads();
    #pragma unroll
    for(int ks=0;ks<16;ks+=8){
      uint32_t a0=__float_as_uint(As[ks+tg  ][mw+g  ]);
      uint32_t a1=__float_as_uint(As[ks+tg  ][mw+g+8]);
      uint32_t a2=__float_as_uint(As[ks+tg+4][mw+g  ]);
      uint32_t a3=__float_as_uint(As[ks+tg+4][mw+g+8]);
      #pragma unroll
      for(int blk=0;blk<4;blk++){
        uint32_t b0=__float_as_uint(Bs[ks+tg  ][nw+blk*8+g]);
        uint32_t b1=__float_as_uint(Bs[ks+tg+4][nw+blk*8+g]);
        mma_tf32(acc[blk][0],acc[blk][1],acc[blk][2],acc[blk][3],a0,a1,a2,a3,b0,b1);
      }
    }
    __syncthreads();
  }
  #pragma unroll
  for(int blk=0;blk<4;blk++){
    int r0=m0+mw+g, c=n0+nw+blk*8+tg*2;
    g_fin[kslice][(size_t)r0*C1c+c]    =acc[blk][0];
    g_fin[kslice][(size_t)r0*C1c+c+1]  =acc[blk][1];
    g_fin[kslice][(size_t)(r0+8)*C1c+c]  =acc[blk][2];
    g_fin[kslice][(size_t)(r0+8)*C1c+c+1]=acc[blk][3];
  }
}

__global__ void k_comb(const float* __restrict__ fbias, float* __restrict__ out){
  int idx=blockIdx.x*256+threadIdx.x;
  if(idx<NNt*C1c){
    float s=fbias[idx%C1c];
    #pragma unroll
    for(int k=0;k<8;k++) s+=g_fin[k][idx];
    out[idx]=s;
  }
}

extern "C" void kernel_launch(void* const* d_in, const int* in_sizes, int n_in,
                              void* d_out, int out_size){
  const float* rec1d=(const float*)d_in[0];
  const float* lig1d=(const float*)d_in[1];
  const float* rep  =(const float*)d_in[2];
  const float* recT =(const float*)d_in[3];
  const float* ligT =(const float*)d_in[4];
  const float* rw1  =(const float*)d_in[5];
  const float* rwp  =(const float*)d_in[6];
  const float* lw1  =(const float*)d_in[7];
  const float* lwp  =(const float*)d_in[8];
  const float* rrw  =(const float*)d_in[9];
  const float* llw  =(const float*)d_in[10];
  const float* rlw  =(const float*)d_in[11];
  const float* lrw  =(const float*)d_in[12];
  const float* fw   =(const float*)d_in[13];
  const float* fbias=(const float*)d_in[14];
  float* out=(float*)d_out;

  static int smem_set = 0;
  int att_smem = (12*WP2 + 2*64*PADc + 2*128*WQP + 16*PP2 + 48 + 12*68) * 4;
  if(!smem_set){
    cudaFuncSetAttribute(k_att, cudaFuncAttributeMaxDynamicSharedMemorySize, att_smem);
    smem_set = 1;
  }

  k_proj   <<<dim3(18,12,2),256>>>(rec1d,lig1d,rw1,rwp,lw1,lwp);
  k_frame  <<<768,192>>>(recT,ligT);
  k_qk     <<<dim3(12,12,12),256>>>();
  k_att    <<<dim3(2,768),512,att_smem>>>(rep,rrw,llw,rlw,lrw);
  k_og     <<<dim3(12,12,2),256>>>();
  k_asm    <<<768,96>>>();
  k_final  <<<dim3(6,12,8),256>>>(fw);
  k_comb   <<<1152,256>>>(fbias,out);
}

// round 16
// speedup vs baseline: 1.6800x; 1.2677x over previous
#include <cuda_runtime.h>
#include <math.h>
#include <stdint.h>

#define Hh 12
#define NRr 512
#define NNt 768
#define C1c 384
#define C2c 128
#define WC_ 0.23570226039551584f   /* sqrt(1/18) */
#define WLS 0.14433756729740643f   /* sqrt(1/3)/4 */

#define JH   384                   /* j per half (per k_att CTA) */
#define TJ   64                    /* j rows per tile */
#define WP2  392                   /* Wt row pad */
#define PADc 132                   /* rep tile row pad */
#define WQP  16                    /* wq row pad */
#define PP2  68                    /* psm row pad */

static __device__ float g_raw[(size_t)NNt*1152];
static __device__ float g_raw2[(size_t)NNt*1152];
static __device__ float g_R[NNt*9];
static __device__ float g_t[NNt*3];
static __device__ float g_q[(size_t)NNt*Hh*32];
static __device__ float g_kT[(size_t)Hh*32*NNt];
static __device__ float g_vph[(size_t)Hh*NNt*24];
static __device__ float g_W[(size_t)NNt*Hh*NNt];
static __device__ float g_ogp[2][(size_t)NNt*24*Hh];
static __device__ float g_feat[(size_t)NNt*2112];
static __device__ float g_fin[8][(size_t)NNt*C1c];
static __device__ float g_o2p[(size_t)2*NNt*2048];
static __device__ float g_ms[NNt*48];

__device__ __forceinline__ void cp16(float* dst, const float* src){
  unsigned sa=(unsigned)__cvta_generic_to_shared(dst);
  asm volatile("cp.async.cg.shared.global [%0], [%1], 16;\n" :: "r"(sa), "l"(src));
}
__device__ __forceinline__ uint32_t f2tf(float x){
  uint32_t r; asm("cvt.rna.tf32.f32 %0, %1;\n" : "=r"(r) : "f"(x)); return r;
}
__device__ __forceinline__ float f2tff(float x){
  uint32_t r; asm("cvt.rna.tf32.f32 %0, %1;\n" : "=r"(r) : "f"(x)); return __uint_as_float(r);
}
__device__ __forceinline__ void mma_tf32(float& d0,float& d1,float& d2,float& d3,
    uint32_t a0,uint32_t a1,uint32_t a2,uint32_t a3,uint32_t b0,uint32_t b1){
  asm volatile("mma.sync.aligned.m16n8k8.row.col.f32.tf32.tf32.f32 "
    "{%0,%1,%2,%3},{%4,%5,%6,%7},{%8,%9},{%0,%1,%2,%3};\n"
    : "+f"(d0),"+f"(d1),"+f"(d2),"+f"(d3)
    : "r"(a0),"r"(a1),"r"(a2),"r"(a3),"r"(b0),"r"(b1));
}

// ------ projections (tf32 mma, split-K=2, cp.async double-buffered staging) ------
__global__ void k_proj(const float* __restrict__ rec1d, const float* __restrict__ lig1d,
                       const float* __restrict__ rw1, const float* __restrict__ rwp,
                       const float* __restrict__ lw1, const float* __restrict__ lwp){
  __shared__ float As[2][64][20], Bs[2][16][72];
  int m0=blockIdx.y*64, n0=blockIdx.x*64, kslice=blockIdx.z, tid=threadIdx.x;
  int wid=tid>>5, lane=tid&31, g=lane>>2, tg=lane&3;
  int mw=(wid&3)*16, nw=(wid>>2)*32;
  const float* X  = (m0<NRr)? rec1d+(size_t)m0*C1c : lig1d+(size_t)(m0-NRr)*C1c;
  const float* Bm = (m0<NRr)? ((n0<576)? rw1: rwp) : ((n0<576)? lw1: lwp);
  int nb = (n0<576)? n0 : n0-576;
  float* dst = kslice? g_raw2 : g_raw;
  int kbase = kslice*192;
  int amm=tid>>2, ac=(tid&3)*4;        // A staging map (1 cp16/thread)
  int bkk=tid>>4, bc=(tid&15)*4;       // B staging map (1 cp16/thread)
  #define PJ_ISSUE(t,b) { int k0=kbase+(t)*16; \
    cp16(&As[b][amm][ac], X + (size_t)amm*C1c + k0 + ac); \
    cp16(&Bs[b][bkk][bc], Bm + (size_t)(k0+bkk)*576 + nb + bc); \
    asm volatile("cp.async.commit_group;\n"); }
  float acc[4][4]={};
  PJ_ISSUE(0,0);
  for(int t=0;t<12;t++){
    int b=t&1;
    if(t<11){ PJ_ISSUE(t+1, b^1); asm volatile("cp.async.wait_group 1;\n"); }
    else    { asm volatile("cp.async.wait_group 0;\n"); }
    __syncthreads();
    #pragma unroll
    for(int ks=0;ks<16;ks+=8){
      uint32_t a0=f2tf(As[b][mw+g  ][ks+tg  ]);
      uint32_t a1=f2tf(As[b][mw+g+8][ks+tg  ]);
      uint32_t a2=f2tf(As[b][mw+g  ][ks+tg+4]);
      uint32_t a3=f2tf(As[b][mw+g+8][ks+tg+4]);
      #pragma unroll
      for(int blk=0;blk<4;blk++){
        uint32_t b0=f2tf(Bs[b][ks+tg  ][nw+blk*8+g]);
        uint32_t b1=f2tf(Bs[b][ks+tg+4][nw+blk*8+g]);
        mma_tf32(acc[blk][0],acc[blk][1],acc[blk][2],acc[blk][3],a0,a1,a2,a3,b0,b1);
      }
    }
    __syncthreads();
  }
  #pragma unroll
  for(int blk=0;blk<4;blk++){
    int r0=m0+mw+g, c=n0+nw+blk*8+tg*2;
    dst[(size_t)r0*1152+c]    =acc[blk][0];
    dst[(size_t)r0*1152+c+1]  =acc[blk][1];
    dst[(size_t)(r0+8)*1152+c]  =acc[blk][2];
    dst[(size_t)(r0+8)*1152+c+1]=acc[blk][3];
  }
}

// ---------------- frames: R,t, point transform, build q/k vectors & vph ----------------
__global__ void k_frame(const float* __restrict__ recT, const float* __restrict__ ligT){
  int i=blockIdx.x, d=threadIdx.x;           // 192 threads, d = h*16+e
  __shared__ float k2p[12][4];
  const float* T=(i<NRr)? recT+(size_t)i*7 : ligT+(size_t)(i-NRr)*7;
  float qw=T[0],qx=T[1],qy=T[2],qz=T[3];
  float inr=rsqrtf(qw*qw+qx*qx+qy*qy+qz*qz);
  qw*=inr;qx*=inr;qy*=inr;qz*=inr;
  float R[9];
  R[0]=1.f-2.f*(qy*qy+qz*qz); R[1]=2.f*(qx*qy-qw*qz); R[2]=2.f*(qx*qz+qw*qy);
  R[3]=2.f*(qx*qy+qw*qz); R[4]=1.f-2.f*(qx*qx+qz*qz); R[5]=2.f*(qy*qz-qw*qx);
  R[6]=2.f*(qx*qz-qw*qy); R[7]=2.f*(qy*qz+qw*qx); R[8]=1.f-2.f*(qx*qx+qy*qy);
  float t0=T[4],t1=T[5],t2=T[6];
  if(d<9) g_R[i*9+d]=R[d];
  if(d<3) g_t[i*3+d]=(d==0?t0:(d==1?t1:t2));
  const float* rp =g_raw +(size_t)i*1152+576;
  const float* rp2=g_raw2+(size_t)i*1152+576;
  float l0=rp[d]+rp2[d], l1=rp[192+d]+rp2[192+d], l2=rp[384+d]+rp2[384+d];
  float g0=R[0]*l0+R[1]*l1+R[2]*l2+t0;
  float g1=R[3]*l0+R[4]*l1+R[5]*l2+t1;
  float g2=R[6]*l0+R[7]*l1+R[8]*l2+t2;
  int h=d>>4, e=d&15;
  if(e<4){                                   // k-points
    k2p[h][e]=g0*g0+g1*g1+g2*g2;
    g_kT[(size_t)(h*32+0+e)*NNt+i]=g0;
    g_kT[(size_t)(h*32+4+e)*NNt+i]=g1;
    g_kT[(size_t)(h*32+8+e)*NNt+i]=g2;
  } else if(e<8){                            // q-points (pre-scaled)
    int p=e-4;
    float* q=&g_q[((size_t)i*Hh+h)*32];
    q[0+p]=2.f*WC_*g0; q[4+p]=2.f*WC_*g1; q[8+p]=2.f*WC_*g2;
  } else {                                   // v-points
    int p=e-8;
    float* v=&g_vph[((size_t)h*NNt+i)*24];
    v[p]=g0; v[8+p]=g1; v[16+p]=g2;
  }
  __syncthreads();
  const float* r1 =g_raw +(size_t)i*1152;
  const float* r12=g_raw2+(size_t)i*1152;
  int s=e;
  g_kT[(size_t)(h*32+12+s)*NNt+i]=r1[h*48+s]+r12[h*48+s];           // k1
  g_q[((size_t)i*Hh+h)*32+12+s]=WLS*(r1[h*48+16+s]+r12[h*48+16+s]); // q1 (pre-scaled)
  if(s==0){
    float K2=k2p[h][0]+k2p[h][1]+k2p[h][2]+k2p[h][3];
    g_kT[(size_t)(h*32+28)*NNt+i]=-WC_*K2;
    g_q[((size_t)i*Hh+h)*32+28]=1.f;
  } else if(s<4){
    g_kT[(size_t)(h*32+28+s)*NNt+i]=0.f;
    g_q[((size_t)i*Hh+h)*32+28+s]=0.f;
  }
}

// ------- qk logits (tf32 mma, hi/lo compensated) + coalesced smem-staged store -------
__global__ void k_qk(){
  __shared__ float qsm[4*2304];              // Ahi|Alo|Bhi|Blo, reused as store tile
  float* Ahi=qsm; float* Alo=qsm+2304; float* Bhi=qsm+4608; float* Blo=qsm+6912;
  int j0=blockIdx.x*64, i0=blockIdx.y*64, h=blockIdx.z, tid=threadIdx.x;
  int wid=tid>>5, lane=tid&31, g=lane>>2, tg=lane&3;
  int mw=(wid&3)*16, nw=(wid>>2)*32;
  for(int l=tid;l<2048;l+=256){ int kk=l&31, mm=l>>5;
    float v=g_q[((size_t)(i0+mm)*Hh+h)*32+kk];
    float hi=f2tff(v);
    Ahi[kk*72+mm]=hi; Alo[kk*72+mm]=f2tff(v-hi); }
  for(int l=tid;l<2048;l+=256){ int kk=l>>6, nn=l&63;
    float v=g_kT[(size_t)(h*32+kk)*NNt + j0+nn];
    float hi=f2tff(v);
    Bhi[kk*72+nn]=hi; Blo[kk*72+nn]=f2tff(v-hi); }
  __syncthreads();
  float acc[4][4]={};
  #pragma unroll
  for(int ks=0;ks<32;ks+=8){
    uint32_t ah0=__float_as_uint(Ahi[(ks+tg  )*72+mw+g  ]);
    uint32_t ah1=__float_as_uint(Ahi[(ks+tg  )*72+mw+g+8]);
    uint32_t ah2=__float_as_uint(Ahi[(ks+tg+4)*72+mw+g  ]);
    uint32_t ah3=__float_as_uint(Ahi[(ks+tg+4)*72+mw+g+8]);
    uint32_t al0=__float_as_uint(Alo[(ks+tg  )*72+mw+g  ]);
    uint32_t al1=__float_as_uint(Alo[(ks+tg  )*72+mw+g+8]);
    uint32_t al2=__float_as_uint(Alo[(ks+tg+4)*72+mw+g  ]);
    uint32_t al3=__float_as_uint(Alo[(ks+tg+4)*72+mw+g+8]);
    #pragma unroll
    for(int blk=0;blk<4;blk++){
      uint32_t bh0=__float_as_uint(Bhi[(ks+tg  )*72+nw+blk*8+g]);
      uint32_t bh1=__float_as_uint(Bhi[(ks+tg+4)*72+nw+blk*8+g]);
      uint32_t bl0=__float_as_uint(Blo[(ks+tg  )*72+nw+blk*8+g]);
      uint32_t bl1=__float_as_uint(Blo[(ks+tg+4)*72+nw+blk*8+g]);
      mma_tf32(acc[blk][0],acc[blk][1],acc[blk][2],acc[blk][3],ah0,ah1,ah2,ah3,bl0,bl1);
      mma_tf32(acc[blk][0],acc[blk][1],acc[blk][2],acc[blk][3],al0,al1,al2,al3,bh0,bh1);
      mma_tf32(acc[blk][0],acc[blk][1],acc[blk][2],acc[blk][3],ah0,ah1,ah2,ah3,bh0,bh1);
    }
  }
  __syncthreads();                            // all fragment reads done; reuse qsm
  float* S=qsm;                               // [64][65]
  #pragma unroll
  for(int blk=0;blk<4;blk++){
    int r0=mw+g, c=nw+blk*8+tg*2;
    S[r0*65+c]    =acc[blk][0]; S[r0*65+c+1]    =acc[blk][1];
    S[(r0+8)*65+c]=acc[blk][2]; S[(r0+8)*65+c+1]=acc[blk][3];
  }
  __syncthreads();
  for(int l=tid;l<1024;l+=256){ int r=l>>4, c4=(l&15)*4;
    float4 v=make_float4(S[r*65+c4],S[r*65+c4+1],S[r*65+c4+2],S[r*65+c4+3]);
    *(float4*)&g_W[((size_t)(i0+r)*Hh+h)*NNt + j0 + c4] = v;
  }
}

// ---- fused half-row attention: bias + partial online softmax + partial o_2d ----
// grid (2,768). 64-row tiles, double-buffered, 2 CTAs/SM, single-phase bias accum.
__global__ void __launch_bounds__(512,2) k_att(const float* __restrict__ rep,
                      const float* __restrict__ rr, const float* __restrict__ ll,
                      const float* __restrict__ rl, const float* __restrict__ lr){
  extern __shared__ float sm[];
  float* Wt   = sm;                        // [12][WP2]
  float* reps0= Wt + 12*WP2;               // [64][PADc]
  float* reps1= reps0 + 64*PADc;           // [64][PADc]
  float* wq   = reps1 + 64*PADc;           // [2][128][WQP]
  float* psm  = wq + 2*128*WQP;            // [16][PP2]
  float* ctrl = psm + 16*PP2;              // m[16], s[16], sc[16]
  float* sm_m = ctrl; float* sm_s = ctrl+16; float* sm_sc = ctrl+32;
  float* Wt2  = ctrl + 48;                 // [12][68] per-tile K-half-1 partials
  int half=blockIdx.x, i=blockIdx.y, tid=threadIdx.x;
  int jbase = half*JH;
  const float* wA = (i<NRr)? rr : lr;      // j < 512
  const float* wB = (i<NRr)? rl : ll;      // j >= 512
  // prologue: prefetch tiles 0 and 1
  {
    const float* rb = rep + ((size_t)i*NNt + jbase)*C2c;
    #pragma unroll
    for(int k=0;k<4;k++){ int l=tid+512*k; int jj=l>>5, c4=(l&31)*4;
      cp16(&reps0[jj*PADc+c4], rb + (size_t)jj*C2c + c4); }
    asm volatile("cp.async.commit_group;\n");
    rb += (size_t)TJ*C2c;
    #pragma unroll
    for(int k=0;k<4;k++){ int l=tid+512*k; int jj=l>>5, c4=(l&31)*4;
      cp16(&reps1[jj*PADc+c4], rb + (size_t)jj*C2c + c4); }
    asm volatile("cp.async.commit_group;\n");
  }
  if(tid<16){ sm_m[tid]=(tid<12)?-1e30f:0.f; sm_s[tid]=(tid<12)?0.f:1.f; sm_sc[tid]=1.f; }
  for(int l=tid;l<2*128*WQP;l+=512){
    int q=l/(128*WQP), rem=l%(128*WQP), c=rem/WQP, h=rem%WQP;
    float v = (h<12)? ((q==0)? wA[c*12+h] : wB[c*12+h]) : 0.f;
    wq[l]=__uint_as_float(f2tf(v));
  }
  for(int l=tid;l<16*PP2;l+=512) psm[l]=0.f;
  for(int l=tid;l<1152;l+=512){ int h=l/96, j4=(l%96)*4;
    *(float4*)&Wt[h*WP2+j4] = *(const float4*)&g_W[((size_t)i*Hh+h)*NNt + jbase + j4]; }

  int wid=tid>>5, lane=tid&31, g=lane>>2, tg=lane&3;
  int m0=(wid&3)*16, n0=((wid>>2)&1)*8, kb=(wid>>3)*64;   // bias mapping (K split)
  int cb0=wid*8;                                          // o2d mapping
  float o0=0.f,o1=0.f,o2=0.f,o3=0.f;

  for(int t=0;t<6;t++){
    float* rp = (t&1)? reps1 : reps0;
    if(t<5) asm volatile("cp.async.wait_group 1;\n");
    else    asm volatile("cp.async.wait_group 0;\n");
    __syncthreads();
    // ---- bias mma: K-half 0 adds into Wt, K-half 1 writes Wt2 (no serialization) ----
    {
      const float* wqs = wq + ((jbase + t*TJ >= NRr)? 128*WQP : 0);
      float c0=0.f,c1=0.f,c2=0.f,c3=0.f;
      #pragma unroll
      for(int k=0;k<8;k++){
        int k0=kb+k*8;
        uint32_t a0=__float_as_uint(rp[(m0+g  )*PADc + k0+tg  ]);
        uint32_t a1=__float_as_uint(rp[(m0+g+8)*PADc + k0+tg  ]);
        uint32_t a2=__float_as_uint(rp[(m0+g  )*PADc + k0+tg+4]);
        uint32_t a3=__float_as_uint(rp[(m0+g+8)*PADc + k0+tg+4]);
        uint32_t b0=__float_as_uint(wqs[(k0+tg  )*WQP + n0+g]);
        uint32_t b1=__float_as_uint(wqs[(k0+tg+4)*WQP + n0+g]);
        mma_tf32(c0,c1,c2,c3,a0,a1,a2,a3,b0,b1);
      }
      int h0=n0+tg*2, h1=h0+1, j0l=m0+g, j1l=m0+g+8;
      if(wid<8){
        if(h0<12){ Wt[h0*WP2+t*TJ+j0l]+=c0; Wt[h0*WP2+t*TJ+j1l]+=c2; }
        if(h1<12){ Wt[h1*WP2+t*TJ+j0l]+=c1; Wt[h1*WP2+t*TJ+j1l]+=c3; }
      } else {
        if(h0<12){ Wt2[h0*68+j0l]=c0; Wt2[h0*68+j1l]=c2; }
        if(h1<12){ Wt2[h1*68+j0l]=c1; Wt2[h1*68+j1l]=c3; }
      }
    }
    __syncthreads();
    // ---- online softmax (warp per head, 64 cols): merge Wt+Wt2, write back ----
    if(wid<12){
      float v[2]; float tmax=-1e30f;
      #pragma unroll
      for(int k=0;k<2;k++){
        v[k]=Wt[wid*WP2+t*TJ+lane+32*k]+Wt2[wid*68+lane+32*k];
        Wt[wid*WP2+t*TJ+lane+32*k]=v[k];
        tmax=fmaxf(tmax,v[k]); }
      #pragma unroll
      for(int o=16;o;o>>=1) tmax=fmaxf(tmax,__shfl_xor_sync(0xffffffffu,tmax,o));
      float mold=sm_m[wid], mnew=fmaxf(mold,tmax);
      float ps=0.f;
      #pragma unroll
      for(int k=0;k<2;k++){ float p=__expf(v[k]-mnew);
        psm[wid*PP2+lane+32*k]=__uint_as_float(f2tf(p)); ps+=p; }
      #pragma unroll
      for(int o=16;o;o>>=1) ps+=__shfl_xor_sync(0xffffffffu,ps,o);
      if(lane==0){ float sc=__expf(mold-mnew); sm_sc[wid]=sc; sm_m[wid]=mnew; sm_s[wid]=sm_s[wid]*sc+ps; }
    }
    __syncthreads();
    // ---- o2d mma: rescale then accumulate (K=64) ----
    {
      float s_lo=sm_sc[g], s_hi=sm_sc[g+8];
      o0*=s_lo; o1*=s_lo; o2*=s_hi; o3*=s_hi;
      #pragma unroll
      for(int k=0;k<8;k++){
        int k0=k*8;
        uint32_t a0=__float_as_uint(psm[(g  )*PP2 + k0+tg  ]);
        uint32_t a1=__float_as_uint(psm[(g+8)*PP2 + k0+tg  ]);
        uint32_t a2=__float_as_uint(psm[(g  )*PP2 + k0+tg+4]);
        uint32_t a3=__float_as_uint(psm[(g+8)*PP2 + k0+tg+4]);
        uint32_t b0=__float_as_uint(rp[(k0+tg  )*PADc + cb0+g]);
        uint32_t b1=__float_as_uint(rp[(k0+tg+4)*PADc + cb0+g]);
        mma_tf32(o0,o1,o2,o3,a0,a1,a2,a3,b0,b1);
      }
    }
    __syncthreads();
    // ---- prefetch tile t+2 into this tile's (now free) buffer ----
    if(t<4){
      const float* rb = rep + ((size_t)i*NNt + jbase + (t+2)*TJ)*C2c;
      #pragma unroll
      for(int k=0;k<4;k++){ int l=tid+512*k; int jj=l>>5, c4=(l&31)*4;
        cp16(&rp[jj*PADc+c4], rb + (size_t)jj*C2c + c4); }
      asm volatile("cp.async.commit_group;\n");
    }
  }
  // ---- partial outputs ----
  if(tid<12){
    g_ms[(size_t)i*48 + tid*4 + half*2 + 0]=sm_m[tid];
    g_ms[(size_t)i*48 + tid*4 + half*2 + 1]=sm_s[tid];
  }
  {
    int cc=cb0+tg*2;
    float* ob = g_o2p + ((size_t)(half*NNt+i))*2048;
    ob[g*128+cc]=o0; ob[g*128+cc+1]=o1;
    ob[(g+8)*128+cc]=o2; ob[(g+8)*128+cc+1]=o3;
  }
  for(int l=tid;l<4608;l+=512){ int h=l/JH, jl=l-h*JH;
    g_W[((size_t)i*Hh+h)*NNt + jbase + jl] = __expf(Wt[h*WP2+jl]-sm_m[h]);
  }
}

// ---- out_global: coalesced scalar, j-half split (grid 12×12×2), local softmax factors ----
__global__ void k_og(){
  __shared__ float Ws[64][129];
  __shared__ float Bsm[128][25];
  __shared__ float facs[64];
  int h=blockIdx.y, i0=blockIdx.x*64, half=blockIdx.z, tid=threadIdx.x;
  int ii=tid&63, dg=(tid>>6)*6;
  if(tid<64){
    int i=i0+tid;
    float m0=g_ms[(size_t)i*48+h*4+0], s0=g_ms[(size_t)i*48+h*4+1];
    float m1=g_ms[(size_t)i*48+h*4+2], s1=g_ms[(size_t)i*48+h*4+3];
    float m=fmaxf(m0,m1);
    float f0=__expf(m0-m), f1=__expf(m1-m);
    float inv=1.f/(s0*f0+s1*f1);
    facs[tid]=(half? f1 : f0)*inv;
  }
  float acc[6]={};
  for(int jt=0;jt<3;jt++){
    int j0=half*JH + jt*128;
    for(int l=tid;l<2048;l+=256){ int r=l>>5, c4=(l&31)*4;
      float4 v=*(const float4*)&g_W[((size_t)(i0+r)*Hh+h)*NNt + j0 + c4];
      Ws[r][c4]=v.x; Ws[r][c4+1]=v.y; Ws[r][c4+2]=v.z; Ws[r][c4+3]=v.w; }
    for(int l=tid;l<3072;l+=256){ int jj=l/24, dp=l%24;
      Bsm[jj][dp]=g_vph[((size_t)h*NNt+j0+jj)*24+dp]; }
    __syncthreads();
    #pragma unroll 4
    for(int jj=0;jj<128;jj++){
      float w=Ws[ii][jj];
      #pragma unroll
      for(int k=0;k<6;k++) acc[k]+=w*Bsm[jj][dg+k];
    }
    __syncthreads();
  }
  float fi=facs[ii];
  for(int k=0;k<6;k++) g_ogp[half][((size_t)(i0+ii)*24+dg+k)*Hh+h]=acc[k]*fi;
}

// ---- frame invert + o_pt/o_norm/o_1d + o_2d merge -> feat (absorbs old k_comb2) ----
__global__ void k_asm(){
  int i=blockIdx.x, tid=threadIdx.x;         // 96 threads, (p,h)
  __shared__ float Rs[9], ts[3];
  __shared__ float ff[12][2];
  if(tid<9) Rs[tid]=g_R[i*9+tid];
  if(tid<3) ts[tid]=g_t[i*3+tid];
  if(tid>=32 && tid<44){
    int hh=tid-32;
    float m0=g_ms[(size_t)i*48+hh*4+0], s0=g_ms[(size_t)i*48+hh*4+1];
    float m1=g_ms[(size_t)i*48+hh*4+2], s1=g_ms[(size_t)i*48+hh*4+3];
    float m=fmaxf(m0,m1);
    float f0=__expf(m0-m), f1=__expf(m1-m);
    float inv=1.f/(s0*f0+s1*f1);
    ff[hh][0]=f0*inv; ff[hh][1]=f1*inv;
  }
  __syncthreads();
  float* fbp=&g_feat[(size_t)i*2112];
  // o_2d merge (was k_comb2)
  {
    const float* p0=g_o2p + (size_t)i*2048;
    const float* p1=g_o2p + (size_t)(NNt+i)*2048;
    for(int l=tid;l<1536;l+=96){ int h=l>>7;
      fbp[l] = p0[l]*ff[h][0] + p1[l]*ff[h][1]; }
  }
  int p=tid/12, h=tid%12;
  float o0=g_ogp[0][((size_t)i*24+ 0+p)*Hh+h]+g_ogp[1][((size_t)i*24+ 0+p)*Hh+h]-ts[0];
  float o1=g_ogp[0][((size_t)i*24+ 8+p)*Hh+h]+g_ogp[1][((size_t)i*24+ 8+p)*Hh+h]-ts[1];
  float o2=g_ogp[0][((size_t)i*24+16+p)*Hh+h]+g_ogp[1][((size_t)i*24+16+p)*Hh+h]-ts[2];
  float n2=0.f;
  #pragma unroll
  for(int d=0;d<3;d++){
    float ol=Rs[0*3+d]*o0+Rs[1*3+d]*o1+Rs[2*3+d]*o2;   // R^T
    fbp[1728+(p*12+h)*3+d]=ol; n2+=ol*ol;
  }
  fbp[2016+p*12+h]=sqrtf(n2);
  for(int l=tid;l<192;l+=96){
    size_t idx=(size_t)i*1152 + (l/16)*48+32+(l%16);
    fbp[1536+l]=g_raw[idx]+g_raw2[idx];      // o_1d = v_1d
  }
}

// ------- final GEMM (tf32 mma, split-K=8, cp.async double-buffered staging) -------
__global__ void k_final(const float* __restrict__ fw){
  __shared__ float As[2][64][20], Bs[2][16][72];
  int n0=blockIdx.x*64, m0=blockIdx.y*64, kslice=blockIdx.z, tid=threadIdx.x;
  int wid=tid>>5, lane=tid&31, g=lane>>2, tg=lane&3;
  int mw=(wid&3)*16, nw=(wid>>2)*32;
  int kbeg=kslice*272, kend=(kbeg+272<2112)? kbeg+272 : 2112;
  int nk=(kend-kbeg)>>4;
  int amm=tid>>2, ac=(tid&3)*4;
  int bkk=tid>>4, bc=(tid&15)*4;
  #define KF_ISSUE(t,b) { int k0=kbeg+(t)*16; \
    cp16(&As[b][amm][ac], g_feat + (size_t)(m0+amm)*2112 + k0 + ac); \
    cp16(&Bs[b][bkk][bc], fw + (size_t)(k0+bkk)*C1c + n0 + bc); \
    asm volatile("cp.async.commit_group;\n"); }
  float acc[4][4]={};
  KF_ISSUE(0,0);
  for(int t=0;t<nk;t++){
    int b=t&1;
    if(t+1<nk){ KF_ISSUE(t+1, b^1); asm volatile("cp.async.wait_group 1;\n"); }
    else      { asm volatile("cp.async.wait_group 0;\n"); }
    __syncthreads();
    #pragma unroll
    for(int ks=0;ks<16;ks+=8){
      uint32_t a0=f2tf(As[b][mw+g  ][ks+tg  ]);
      uint32_t a1=f2tf(As[b][mw+g+8][ks+tg  ]);
      uint32_t a2=f2tf(As[b][mw+g  ][ks+tg+4]);
      uint32_t a3=f2tf(As[b][mw+g+8][ks+tg+4]);
      #pragma unroll
      for(int blk=0;blk<4;blk++){
        uint32_t b0=f2tf(Bs[b][ks+tg  ][nw+blk*8+g]);
        uint32_t b1=f2tf(Bs[b][ks+tg+4][nw+blk*8+g]);
        mma_tf32(acc[blk][0],acc[blk][1],acc[blk][2],acc[blk][3],a0,a1,a2,a3,b0,b1);
      }
    }
    __syncthreads();
  }
  #pragma unroll
  for(int blk=0;blk<4;blk++){
    int r0=m0+mw+g, c=n0+nw+blk*8+tg*2;
    g_fin[kslice][(size_t)r0*C1c+c]    =acc[blk][0];
    g_fin[kslice][(size_t)r0*C1c+c+1]  =acc[blk][1];
    g_fin[kslice][(size_t)(r0+8)*C1c+c]  =acc[blk][2];
    g_fin[kslice][(size_t)(r0+8)*C1c+c+1]=acc[blk][3];
  }
}

__global__ void k_comb(const float* __restrict__ fbias, float* __restrict__ out){
  int idx=blockIdx.x*256+threadIdx.x;
  if(idx<NNt*C1c){
    float s=fbias[idx%C1c];
    #pragma unroll
    for(int k=0;k<8;k++) s+=g_fin[k][idx];
    out[idx]=s;
  }
}

extern "C" void kernel_launch(void* const* d_in, const int* in_sizes, int n_in,
                              void* d_out, int out_size){
  const float* rec1d=(const float*)d_in[0];
  const float* lig1d=(const float*)d_in[1];
  const float* rep  =(const float*)d_in[2];
  const float* recT =(const float*)d_in[3];
  const float* ligT =(const float*)d_in[4];
  const float* rw1  =(const float*)d_in[5];
  const float* rwp  =(const float*)d_in[6];
  const float* lw1  =(const float*)d_in[7];
  const float* lwp  =(const float*)d_in[8];
  const float* rrw  =(const float*)d_in[9];
  const float* llw  =(const float*)d_in[10];
  const float* rlw  =(const float*)d_in[11];
  const float* lrw  =(const float*)d_in[12];
  const float* fw   =(const float*)d_in[13];
  const float* fbias=(const float*)d_in[14];
  float* out=(float*)d_out;

  static int smem_set = 0;
  int att_smem = (12*WP2 + 2*64*PADc + 2*128*WQP + 16*PP2 + 48 + 12*68) * 4;
  if(!smem_set){
    cudaFuncSetAttribute(k_att, cudaFuncAttributeMaxDynamicSharedMemorySize, att_smem);
    smem_set = 1;
  }

  k_proj   <<<dim3(18,12,2),256>>>(rec1d,lig1d,rw1,rwp,lw1,lwp);
  k_frame  <<<768,192>>>(recT,ligT);
  k_qk     <<<dim3(12,12,12),256>>>();
  k_att    <<<dim3(2,768),512,att_smem>>>(rep,rrw,llw,rlw,lrw);
  k_og     <<<dim3(12,12,2),256>>>();
  k_asm    <<<768,96>>>();
  k_final  <<<dim3(6,12,8),256>>>(fw);
  k_comb   <<<1152,256>>>(fbias,out);
}

// round 17
// speedup vs baseline: 1.6967x; 1.0100x over previous
#include <cuda_runtime.h>
#include <math.h>
#include <stdint.h>

#define Hh 12
#define NRr 512
#define NNt 768
#define C1c 384
#define C2c 128
#define WC_ 0.23570226039551584f   /* sqrt(1/18) */
#define WLS 0.14433756729740643f   /* sqrt(1/3)/4 */

#define JH   384                   /* j per half (per k_att CTA) */
#define TJ   64                    /* j rows per tile */
#define WP2  392                   /* Wt row pad */
#define PADc 132                   /* rep tile row pad */
#define WQP  16                    /* wq row pad */
#define PP2  68                    /* psm row pad */

static __device__ float g_raw[(size_t)NNt*1152];
static __device__ float g_raw2[(size_t)NNt*1152];
static __device__ float g_R[NNt*9];
static __device__ float g_t[NNt*3];
static __device__ float g_qT_hi[(size_t)Hh*32*NNt];
static __device__ float g_qT_lo[(size_t)Hh*32*NNt];
static __device__ float g_kT_hi[(size_t)Hh*32*NNt];
static __device__ float g_kT_lo[(size_t)Hh*32*NNt];
static __device__ float g_vph[(size_t)Hh*NNt*24];
static __device__ float g_W[(size_t)NNt*Hh*NNt];
static __device__ float g_ogp[2][(size_t)NNt*24*Hh];
static __device__ float g_feat[(size_t)NNt*2112];
static __device__ float g_fin[8][(size_t)NNt*C1c];
static __device__ float g_o2p[(size_t)2*NNt*2048];
static __device__ float g_ms[NNt*48];

__device__ __forceinline__ void cp16(float* dst, const float* src){
  unsigned sa=(unsigned)__cvta_generic_to_shared(dst);
  asm volatile("cp.async.cg.shared.global [%0], [%1], 16;\n" :: "r"(sa), "l"(src));
}
__device__ __forceinline__ uint32_t f2tf(float x){
  uint32_t r; asm("cvt.rna.tf32.f32 %0, %1;\n" : "=r"(r) : "f"(x)); return r;
}
__device__ __forceinline__ float f2tff(float x){
  uint32_t r; asm("cvt.rna.tf32.f32 %0, %1;\n" : "=r"(r) : "f"(x)); return __uint_as_float(r);
}
__device__ __forceinline__ void mma_tf32(float& d0,float& d1,float& d2,float& d3,
    uint32_t a0,uint32_t a1,uint32_t a2,uint32_t a3,uint32_t b0,uint32_t b1){
  asm volatile("mma.sync.aligned.m16n8k8.row.col.f32.tf32.tf32.f32 "
    "{%0,%1,%2,%3},{%4,%5,%6,%7},{%8,%9},{%0,%1,%2,%3};\n"
    : "+f"(d0),"+f"(d1),"+f"(d2),"+f"(d3)
    : "r"(a0),"r"(a1),"r"(a2),"r"(a3),"r"(b0),"r"(b1));
}

// ------ projections (tf32 mma, split-K=2, cp.async double-buffered staging) ------
__global__ void k_proj(const float* __restrict__ rec1d, const float* __restrict__ lig1d,
                       const float* __restrict__ rw1, const float* __restrict__ rwp,
                       const float* __restrict__ lw1, const float* __restrict__ lwp){
  __shared__ float As[2][64][20], Bs[2][16][72];
  int m0=blockIdx.y*64, n0=blockIdx.x*64, kslice=blockIdx.z, tid=threadIdx.x;
  int wid=tid>>5, lane=tid&31, g=lane>>2, tg=lane&3;
  int mw=(wid&3)*16, nw=(wid>>2)*32;
  const float* X  = (m0<NRr)? rec1d+(size_t)m0*C1c : lig1d+(size_t)(m0-NRr)*C1c;
  const float* Bm = (m0<NRr)? ((n0<576)? rw1: rwp) : ((n0<576)? lw1: lwp);
  int nb = (n0<576)? n0 : n0-576;
  float* dst = kslice? g_raw2 : g_raw;
  int kbase = kslice*192;
  int amm=tid>>2, ac=(tid&3)*4;        // A staging map (1 cp16/thread)
  int bkk=tid>>4, bc=(tid&15)*4;       // B staging map (1 cp16/thread)
  #define PJ_ISSUE(t,b) { int k0=kbase+(t)*16; \
    cp16(&As[b][amm][ac], X + (size_t)amm*C1c + k0 + ac); \
    cp16(&Bs[b][bkk][bc], Bm + (size_t)(k0+bkk)*576 + nb + bc); \
    asm volatile("cp.async.commit_group;\n"); }
  float acc[4][4]={};
  PJ_ISSUE(0,0);
  for(int t=0;t<12;t++){
    int b=t&1;
    if(t<11){ PJ_ISSUE(t+1, b^1); asm volatile("cp.async.wait_group 1;\n"); }
    else    { asm volatile("cp.async.wait_group 0;\n"); }
    __syncthreads();
    #pragma unroll
    for(int ks=0;ks<16;ks+=8){
      uint32_t a0=f2tf(As[b][mw+g  ][ks+tg  ]);
      uint32_t a1=f2tf(As[b][mw+g+8][ks+tg  ]);
      uint32_t a2=f2tf(As[b][mw+g  ][ks+tg+4]);
      uint32_t a3=f2tf(As[b][mw+g+8][ks+tg+4]);
      #pragma unroll
      for(int blk=0;blk<4;blk++){
        uint32_t b0=f2tf(Bs[b][ks+tg  ][nw+blk*8+g]);
        uint32_t b1=f2tf(Bs[b][ks+tg+4][nw+blk*8+g]);
        mma_tf32(acc[blk][0],acc[blk][1],acc[blk][2],acc[blk][3],a0,a1,a2,a3,b0,b1);
      }
    }
    __syncthreads();
  }
  #pragma unroll
  for(int blk=0;blk<4;blk++){
    int r0=m0+mw+g, c=n0+nw+blk*8+tg*2;
    dst[(size_t)r0*1152+c]    =acc[blk][0];
    dst[(size_t)r0*1152+c+1]  =acc[blk][1];
    dst[(size_t)(r0+8)*1152+c]  =acc[blk][2];
    dst[(size_t)(r0+8)*1152+c+1]=acc[blk][3];
  }
}

// ---- frames: R,t, point transform; q/k hi-lo tf32 split stored transposed ----
__global__ void k_frame(const float* __restrict__ recT, const float* __restrict__ ligT){
  int i=blockIdx.x, d=threadIdx.x;           // 192 threads, d = h*16+e
  __shared__ float k2p[12][4];
  const float* T=(i<NRr)? recT+(size_t)i*7 : ligT+(size_t)(i-NRr)*7;
  float qw=T[0],qx=T[1],qy=T[2],qz=T[3];
  float inr=rsqrtf(qw*qw+qx*qx+qy*qy+qz*qz);
  qw*=inr;qx*=inr;qy*=inr;qz*=inr;
  float R[9];
  R[0]=1.f-2.f*(qy*qy+qz*qz); R[1]=2.f*(qx*qy-qw*qz); R[2]=2.f*(qx*qz+qw*qy);
  R[3]=2.f*(qx*qy+qw*qz); R[4]=1.f-2.f*(qx*qx+qz*qz); R[5]=2.f*(qy*qz-qw*qx);
  R[6]=2.f*(qx*qz-qw*qy); R[7]=2.f*(qy*qz+qw*qx); R[8]=1.f-2.f*(qx*qx+qy*qy);
  float t0=T[4],t1=T[5],t2=T[6];
  if(d<9) g_R[i*9+d]=R[d];
  if(d<3) g_t[i*3+d]=(d==0?t0:(d==1?t1:t2));
  const float* rp =g_raw +(size_t)i*1152+576;
  const float* rp2=g_raw2+(size_t)i*1152+576;
  float l0=rp[d]+rp2[d], l1=rp[192+d]+rp2[192+d], l2=rp[384+d]+rp2[384+d];
  float g0=R[0]*l0+R[1]*l1+R[2]*l2+t0;
  float g1=R[3]*l0+R[4]*l1+R[5]*l2+t1;
  float g2=R[6]*l0+R[7]*l1+R[8]*l2+t2;
  int h=d>>4, e=d&15;
  #define WKT(row,val){ float hv_=f2tff(val); size_t a_=(size_t)(row)*NNt+i; \
    g_kT_hi[a_]=hv_; g_kT_lo[a_]=f2tff((val)-hv_); }
  #define WQT(row,val){ float hv_=f2tff(val); size_t a_=(size_t)(row)*NNt+i; \
    g_qT_hi[a_]=hv_; g_qT_lo[a_]=f2tff((val)-hv_); }
  if(e<4){                                   // k-points
    k2p[h][e]=g0*g0+g1*g1+g2*g2;
    WKT(h*32+0+e, g0); WKT(h*32+4+e, g1); WKT(h*32+8+e, g2);
  } else if(e<8){                            // q-points (pre-scaled)
    int p=e-4;
    WQT(h*32+0+p, 2.f*WC_*g0); WQT(h*32+4+p, 2.f*WC_*g1); WQT(h*32+8+p, 2.f*WC_*g2);
  } else {                                   // v-points
    int p=e-8;
    float* v=&g_vph[((size_t)h*NNt+i)*24];
    v[p]=g0; v[8+p]=g1; v[16+p]=g2;
  }
  __syncthreads();
  const float* r1 =g_raw +(size_t)i*1152;
  const float* r12=g_raw2+(size_t)i*1152;
  int s=e;
  WKT(h*32+12+s, r1[h*48+s]+r12[h*48+s]);                    // k1
  WQT(h*32+12+s, WLS*(r1[h*48+16+s]+r12[h*48+16+s]));        // q1 (pre-scaled)
  if(s==0){
    float K2=k2p[h][0]+k2p[h][1]+k2p[h][2]+k2p[h][3];
    WKT(h*32+28, -WC_*K2);
    size_t a_=(size_t)(h*32+28)*NNt+i;
    g_qT_hi[a_]=1.f; g_qT_lo[a_]=0.f;
  } else if(s<4){
    size_t a_=(size_t)(h*32+28+s)*NNt+i;
    g_kT_hi[a_]=0.f; g_kT_lo[a_]=0.f;
    g_qT_hi[a_]=0.f; g_qT_lo[a_]=0.f;
  }
}

// ---- qk logits (tf32 mma, hi/lo compensated); cp.async staging; coalesced store ----
__global__ void k_qk(){
  __shared__ float qsm[4*2304];              // Ahi|Alo|Bhi|Blo, reused as store tile
  float* Ahi=qsm; float* Alo=qsm+2304; float* Bhi=qsm+4608; float* Blo=qsm+6912;
  int j0=blockIdx.x*64, i0=blockIdx.y*64, h=blockIdx.z, tid=threadIdx.x;
  int wid=tid>>5, lane=tid&31, g=lane>>2, tg=lane&3;
  int mw=(wid&3)*16, nw=(wid>>2)*32;
  for(int l=tid;l<512;l+=256){
    int kk=l>>4, m4=(l&15)*4;
    size_t ar=(size_t)(h*32+kk)*NNt;
    cp16(&Ahi[kk*72+m4], g_qT_hi+ar+i0+m4);
    cp16(&Alo[kk*72+m4], g_qT_lo+ar+i0+m4);
    cp16(&Bhi[kk*72+m4], g_kT_hi+ar+j0+m4);
    cp16(&Blo[kk*72+m4], g_kT_lo+ar+j0+m4);
  }
  asm volatile("cp.async.commit_group;\n");
  asm volatile("cp.async.wait_group 0;\n");
  __syncthreads();
  float acc[4][4]={};
  #pragma unroll
  for(int ks=0;ks<32;ks+=8){
    uint32_t ah0=__float_as_uint(Ahi[(ks+tg  )*72+mw+g  ]);
    uint32_t ah1=__float_as_uint(Ahi[(ks+tg  )*72+mw+g+8]);
    uint32_t ah2=__float_as_uint(Ahi[(ks+tg+4)*72+mw+g  ]);
    uint32_t ah3=__float_as_uint(Ahi[(ks+tg+4)*72+mw+g+8]);
    uint32_t al0=__float_as_uint(Alo[(ks+tg  )*72+mw+g  ]);
    uint32_t al1=__float_as_uint(Alo[(ks+tg  )*72+mw+g+8]);
    uint32_t al2=__float_as_uint(Alo[(ks+tg+4)*72+mw+g  ]);
    uint32_t al3=__float_as_uint(Alo[(ks+tg+4)*72+mw+g+8]);
    #pragma unroll
    for(int blk=0;blk<4;blk++){
      uint32_t bh0=__float_as_uint(Bhi[(ks+tg  )*72+nw+blk*8+g]);
      uint32_t bh1=__float_as_uint(Bhi[(ks+tg+4)*72+nw+blk*8+g]);
      uint32_t bl0=__float_as_uint(Blo[(ks+tg  )*72+nw+blk*8+g]);
      uint32_t bl1=__float_as_uint(Blo[(ks+tg+4)*72+nw+blk*8+g]);
      mma_tf32(acc[blk][0],acc[blk][1],acc[blk][2],acc[blk][3],ah0,ah1,ah2,ah3,bl0,bl1);
      mma_tf32(acc[blk][0],acc[blk][1],acc[blk][2],acc[blk][3],al0,al1,al2,al3,bh0,bh1);
      mma_tf32(acc[blk][0],acc[blk][1],acc[blk][2],acc[blk][3],ah0,ah1,ah2,ah3,bh0,bh1);
    }
  }
  __syncthreads();                            // all fragment reads done; reuse qsm
  float* S=qsm;                               // [64][65]
  #pragma unroll
  for(int blk=0;blk<4;blk++){
    int r0=mw+g, c=nw+blk*8+tg*2;
    S[r0*65+c]    =acc[blk][0]; S[r0*65+c+1]    =acc[blk][1];
    S[(r0+8)*65+c]=acc[blk][2]; S[(r0+8)*65+c+1]=acc[blk][3];
  }
  __syncthreads();
  for(int l=tid;l<1024;l+=256){ int r=l>>4, c4=(l&15)*4;
    float4 v=make_float4(S[r*65+c4],S[r*65+c4+1],S[r*65+c4+2],S[r*65+c4+3]);
    *(float4*)&g_W[((size_t)(i0+r)*Hh+h)*NNt + j0 + c4] = v;
  }
}

// ---- fused half-row attention: bias + partial online softmax + partial o_2d ----
// grid (2,768). 64-row tiles, double-buffered, 2 CTAs/SM, single-phase bias accum.
__global__ void __launch_bounds__(512,2) k_att(const float* __restrict__ rep,
                      const float* __restrict__ rr, const float* __restrict__ ll,
                      const float* __restrict__ rl, const float* __restrict__ lr){
  extern __shared__ float sm[];
  float* Wt   = sm;                        // [12][WP2]
  float* reps0= Wt + 12*WP2;               // [64][PADc]
  float* reps1= reps0 + 64*PADc;           // [64][PADc]
  float* wq   = reps1 + 64*PADc;           // [2][128][WQP]
  float* psm  = wq + 2*128*WQP;            // [16][PP2]
  float* ctrl = psm + 16*PP2;              // m[16], s[16], sc[16]
  float* sm_m = ctrl; float* sm_s = ctrl+16; float* sm_sc = ctrl+32;
  float* Wt2  = ctrl + 48;                 // [12][68] per-tile K-half-1 partials
  int half=blockIdx.x, i=blockIdx.y, tid=threadIdx.x;
  int jbase = half*JH;
  const float* wA = (i<NRr)? rr : lr;      // j < 512
  const float* wB = (i<NRr)? rl : ll;      // j >= 512
  // prologue: prefetch tiles 0 and 1
  {
    const float* rb = rep + ((size_t)i*NNt + jbase)*C2c;
    #pragma unroll
    for(int k=0;k<4;k++){ int l=tid+512*k; int jj=l>>5, c4=(l&31)*4;
      cp16(&reps0[jj*PADc+c4], rb + (size_t)jj*C2c + c4); }
    asm volatile("cp.async.commit_group;\n");
    rb += (size_t)TJ*C2c;
    #pragma unroll
    for(int k=0;k<4;k++){ int l=tid+512*k; int jj=l>>5, c4=(l&31)*4;
      cp16(&reps1[jj*PADc+c4], rb + (size_t)jj*C2c + c4); }
    asm volatile("cp.async.commit_group;\n");
  }
  if(tid<16){ sm_m[tid]=(tid<12)?-1e30f:0.f; sm_s[tid]=(tid<12)?0.f:1.f; sm_sc[tid]=1.f; }
  for(int l=tid;l<2*128*WQP;l+=512){
    int q=l/(128*WQP), rem=l%(128*WQP), c=rem/WQP, h=rem%WQP;
    float v = (h<12)? ((q==0)? wA[c*12+h] : wB[c*12+h]) : 0.f;
    wq[l]=__uint_as_float(f2tf(v));
  }
  for(int l=tid;l<16*PP2;l+=512) psm[l]=0.f;
  for(int l=tid;l<1152;l+=512){ int h=l/96, j4=(l%96)*4;
    *(float4*)&Wt[h*WP2+j4] = *(const float4*)&g_W[((size_t)i*Hh+h)*NNt + jbase + j4]; }

  int wid=tid>>5, lane=tid&31, g=lane>>2, tg=lane&3;
  int m0=(wid&3)*16, n0=((wid>>2)&1)*8, kb=(wid>>3)*64;   // bias mapping (K split)
  int cb0=wid*8;                                          // o2d mapping
  float o0=0.f,o1=0.f,o2=0.f,o3=0.f;

  for(int t=0;t<6;t++){
    float* rp = (t&1)? reps1 : reps0;
    if(t<5) asm volatile("cp.async.wait_group 1;\n");
    else    asm volatile("cp.async.wait_group 0;\n");
    __syncthreads();
    // ---- bias mma: K-half 0 adds into Wt, K-half 1 writes Wt2 (no serialization) ----
    {
      const float* wqs = wq + ((jbase + t*TJ >= NRr)? 128*WQP : 0);
      float c0=0.f,c1=0.f,c2=0.f,c3=0.f;
      #pragma unroll
      for(int k=0;k<8;k++){
        int k0=kb+k*8;
        uint32_t a0=__float_as_uint(rp[(m0+g  )*PADc + k0+tg  ]);
        uint32_t a1=__float_as_uint(rp[(m0+g+8)*PADc + k0+tg  ]);
        uint32_t a2=__float_as_uint(rp[(m0+g  )*PADc + k0+tg+4]);
        uint32_t a3=__float_as_uint(rp[(m0+g+8)*PADc + k0+tg+4]);
        uint32_t b0=__float_as_uint(wqs[(k0+tg  )*WQP + n0+g]);
        uint32_t b1=__float_as_uint(wqs[(k0+tg+4)*WQP + n0+g]);
        mma_tf32(c0,c1,c2,c3,a0,a1,a2,a3,b0,b1);
      }
      int h0=n0+tg*2, h1=h0+1, j0l=m0+g, j1l=m0+g+8;
      if(wid<8){
        if(h0<12){ Wt[h0*WP2+t*TJ+j0l]+=c0; Wt[h0*WP2+t*TJ+j1l]+=c2; }
        if(h1<12){ Wt[h1*WP2+t*TJ+j0l]+=c1; Wt[h1*WP2+t*TJ+j1l]+=c3; }
      } else {
        if(h0<12){ Wt2[h0*68+j0l]=c0; Wt2[h0*68+j1l]=c2; }
        if(h1<12){ Wt2[h1*68+j0l]=c1; Wt2[h1*68+j1l]=c3; }
      }
    }
    __syncthreads();
    // ---- online softmax (warp per head, 64 cols): merge Wt+Wt2, write back ----
    if(wid<12){
      float v[2]; float tmax=-1e30f;
      #pragma unroll
      for(int k=0;k<2;k++){
        v[k]=Wt[wid*WP2+t*TJ+lane+32*k]+Wt2[wid*68+lane+32*k];
        Wt[wid*WP2+t*TJ+lane+32*k]=v[k];
        tmax=fmaxf(tmax,v[k]); }
      #pragma unroll
      for(int o=16;o;o>>=1) tmax=fmaxf(tmax,__shfl_xor_sync(0xffffffffu,tmax,o));
      float mold=sm_m[wid], mnew=fmaxf(mold,tmax);
      float ps=0.f;
      #pragma unroll
      for(int k=0;k<2;k++){ float p=__expf(v[k]-mnew);
        psm[wid*PP2+lane+32*k]=__uint_as_float(f2tf(p)); ps+=p; }
      #pragma unroll
      for(int o=16;o;o>>=1) ps+=__shfl_xor_sync(0xffffffffu,ps,o);
      if(lane==0){ float sc=__expf(mold-mnew); sm_sc[wid]=sc; sm_m[wid]=mnew; sm_s[wid]=sm_s[wid]*sc+ps; }
    }
    __syncthreads();
    // ---- o2d mma: rescale then accumulate (K=64) ----
    {
      float s_lo=sm_sc[g], s_hi=sm_sc[g+8];
      o0*=s_lo; o1*=s_lo; o2*=s_hi; o3*=s_hi;
      #pragma unroll
      for(int k=0;k<8;k++){
        int k0=k*8;
        uint32_t a0=__float_as_uint(psm[(g  )*PP2 + k0+tg  ]);
        uint32_t a1=__float_as_uint(psm[(g+8)*PP2 + k0+tg  ]);
        uint32_t a2=__float_as_uint(psm[(g  )*PP2 + k0+tg+4]);
        uint32_t a3=__float_as_uint(psm[(g+8)*PP2 + k0+tg+4]);
        uint32_t b0=__float_as_uint(rp[(k0+tg  )*PADc + cb0+g]);
        uint32_t b1=__float_as_uint(rp[(k0+tg+4)*PADc + cb0+g]);
        mma_tf32(o0,o1,o2,o3,a0,a1,a2,a3,b0,b1);
      }
    }
    __syncthreads();
    // ---- prefetch tile t+2 into this tile's (now free) buffer ----
    if(t<4){
      const float* rb = rep + ((size_t)i*NNt + jbase + (t+2)*TJ)*C2c;
      #pragma unroll
      for(int k=0;k<4;k++){ int l=tid+512*k; int jj=l>>5, c4=(l&31)*4;
        cp16(&rp[jj*PADc+c4], rb + (size_t)jj*C2c + c4); }
      asm volatile("cp.async.commit_group;\n");
    }
  }
  // ---- partial outputs ----
  if(tid<12){
    g_ms[(size_t)i*48 + tid*4 + half*2 + 0]=sm_m[tid];
    g_ms[(size_t)i*48 + tid*4 + half*2 + 1]=sm_s[tid];
  }
  {
    int cc=cb0+tg*2;
    float* ob = g_o2p + ((size_t)(half*NNt+i))*2048;
    ob[g*128+cc]=o0; ob[g*128+cc+1]=o1;
    ob[(g+8)*128+cc]=o2; ob[(g+8)*128+cc+1]=o3;
  }
  for(int l=tid;l<4608;l+=512){ int h=l/JH, jl=l-h*JH;
    g_W[((size_t)i*Hh+h)*NNt + jbase + jl] = __expf(Wt[h*WP2+jl]-sm_m[h]);
  }
}

// ---- out_global: coalesced scalar, j-half split (grid 12×12×2), local softmax factors ----
__global__ void k_og(){
  __shared__ float Ws[64][129];
  __shared__ float Bsm[128][25];
  __shared__ float facs[64];
  int h=blockIdx.y, i0=blockIdx.x*64, half=blockIdx.z, tid=threadIdx.x;
  int ii=tid&63, dg=(tid>>6)*6;
  if(tid<64){
    int i=i0+tid;
    float m0=g_ms[(size_t)i*48+h*4+0], s0=g_ms[(size_t)i*48+h*4+1];
    float m1=g_ms[(size_t)i*48+h*4+2], s1=g_ms[(size_t)i*48+h*4+3];
    float m=fmaxf(m0,m1);
    float f0=__expf(m0-m), f1=__expf(m1-m);
    float inv=1.f/(s0*f0+s1*f1);
    facs[tid]=(half? f1 : f0)*inv;
  }
  float acc[6]={};
  for(int jt=0;jt<3;jt++){
    int j0=half*JH + jt*128;
    for(int l=tid;l<2048;l+=256){ int r=l>>5, c4=(l&31)*4;
      float4 v=*(const float4*)&g_W[((size_t)(i0+r)*Hh+h)*NNt + j0 + c4];
      Ws[r][c4]=v.x; Ws[r][c4+1]=v.y; Ws[r][c4+2]=v.z; Ws[r][c4+3]=v.w; }
    for(int l=tid;l<3072;l+=256){ int jj=l/24, dp=l%24;
      Bsm[jj][dp]=g_vph[((size_t)h*NNt+j0+jj)*24+dp]; }
    __syncthreads();
    #pragma unroll 4
    for(int jj=0;jj<128;jj++){
      float w=Ws[ii][jj];
      #pragma unroll
      for(int k=0;k<6;k++) acc[k]+=w*Bsm[jj][dg+k];
    }
    __syncthreads();
  }
  float fi=facs[ii];
  for(int k=0;k<6;k++) g_ogp[half][((size_t)(i0+ii)*24+dg+k)*Hh+h]=acc[k]*fi;
}

// ---- frame invert + o_pt/o_norm/o_1d + o_2d merge -> feat ----
__global__ void k_asm(){
  int i=blockIdx.x, tid=threadIdx.x;         // 96 threads, (p,h)
  __shared__ float Rs[9], ts[3];
  __shared__ float ff[12][2];
  if(tid<9) Rs[tid]=g_R[i*9+tid];
  if(tid<3) ts[tid]=g_t[i*3+tid];
  if(tid>=32 && tid<44){
    int hh=tid-32;
    float m0=g_ms[(size_t)i*48+hh*4+0], s0=g_ms[(size_t)i*48+hh*4+1];
    float m1=g_ms[(size_t)i*48+hh*4+2], s1=g_ms[(size_t)i*48+hh*4+3];
    float m=fmaxf(m0,m1);
    float f0=__expf(m0-m), f1=__expf(m1-m);
    float inv=1.f/(s0*f0+s1*f1);
    ff[hh][0]=f0*inv; ff[hh][1]=f1*inv;
  }
  __syncthreads();
  float* fbp=&g_feat[(size_t)i*2112];
  {
    const float* p0=g_o2p + (size_t)i*2048;
    const float* p1=g_o2p + (size_t)(NNt+i)*2048;
    for(int l=tid;l<1536;l+=96){ int h=l>>7;
      fbp[l] = p0[l]*ff[h][0] + p1[l]*ff[h][1]; }
  }
  int p=tid/12, h=tid%12;
  float o0=g_ogp[0][((size_t)i*24+ 0+p)*Hh+h]+g_ogp[1][((size_t)i*24+ 0+p)*Hh+h]-ts[0];
  float o1=g_ogp[0][((size_t)i*24+ 8+p)*Hh+h]+g_ogp[1][((size_t)i*24+ 8+p)*Hh+h]-ts[1];
  float o2=g_ogp[0][((size_t)i*24+16+p)*Hh+h]+g_ogp[1][((size_t)i*24+16+p)*Hh+h]-ts[2];
  float n2=0.f;
  #pragma unroll
  for(int d=0;d<3;d++){
    float ol=Rs[0*3+d]*o0+Rs[1*3+d]*o1+Rs[2*3+d]*o2;   // R^T
    fbp[1728+(p*12+h)*3+d]=ol; n2+=ol*ol;
  }
  fbp[2016+p*12+h]=sqrtf(n2);
  for(int l=tid;l<192;l+=96){
    size_t idx=(size_t)i*1152 + (l/16)*48+32+(l%16);
    fbp[1536+l]=g_raw[idx]+g_raw2[idx];      // o_1d = v_1d
  }
}

// ------- final GEMM (tf32 mma, split-K=8, cp.async double-buffered staging) -------
__global__ void k_final(const float* __restrict__ fw){
  __shared__ float As[2][64][20], Bs[2][16][72];
  int n0=blockIdx.x*64, m0=blockIdx.y*64, kslice=blockIdx.z, tid=threadIdx.x;
  int wid=tid>>5, lane=tid&31, g=lane>>2, tg=lane&3;
  int mw=(wid&3)*16, nw=(wid>>2)*32;
  int kbeg=kslice*272, kend=(kbeg+272<2112)? kbeg+272 : 2112;
  int nk=(kend-kbeg)>>4;
  int amm=tid>>2, ac=(tid&3)*4;
  int bkk=tid>>4, bc=(tid&15)*4;
  #define KF_ISSUE(t,b) { int k0=kbeg+(t)*16; \
    cp16(&As[b][amm][ac], g_feat + (size_t)(m0+amm)*2112 + k0 + ac); \
    cp16(&Bs[b][bkk][bc], fw + (size_t)(k0+bkk)*C1c + n0 + bc); \
    asm volatile("cp.async.commit_group;\n"); }
  float acc[4][4]={};
  KF_ISSUE(0,0);
  for(int t=0;t<nk;t++){
    int b=t&1;
    if(t+1<nk){ KF_ISSUE(t+1, b^1); asm volatile("cp.async.wait_group 1;\n"); }
    else      { asm volatile("cp.async.wait_group 0;\n"); }
    __syncthreads();
    #pragma unroll
    for(int ks=0;ks<16;ks+=8){
      uint32_t a0=f2tf(As[b][mw+g  ][ks+tg  ]);
      uint32_t a1=f2tf(As[b][mw+g+8][ks+tg  ]);
      uint32_t a2=f2tf(As[b][mw+g  ][ks+tg+4]);
      uint32_t a3=f2tf(As[b][mw+g+8][ks+tg+4]);
      #pragma unroll
      for(int blk=0;blk<4;blk++){
        uint32_t b0=f2tf(Bs[b][ks+tg  ][nw+blk*8+g]);
        uint32_t b1=f2tf(Bs[b][ks+tg+4][nw+blk*8+g]);
        mma_tf32(acc[blk][0],acc[blk][1],acc[blk][2],acc[blk][3],a0,a1,a2,a3,b0,b1);
      }
    }
    __syncthreads();
  }
  #pragma unroll
  for(int blk=0;blk<4;blk++){
    int r0=m0+mw+g, c=n0+nw+blk*8+tg*2;
    g_fin[kslice][(size_t)r0*C1c+c]    =acc[blk][0];
    g_fin[kslice][(size_t)r0*C1c+c+1]  =acc[blk][1];
    g_fin[kslice][(size_t)(r0+8)*C1c+c]  =acc[blk][2];
    g_fin[kslice][(size_t)(r0+8)*C1c+c+1]=acc[blk][3];
  }
}

__global__ void k_comb(const float* __restrict__ fbias, float* __restrict__ out){
  int idx=blockIdx.x*256+threadIdx.x;
  if(idx<NNt*C1c){
    float s=fbias[idx%C1c];
    #pragma unroll
    for(int k=0;k<8;k++) s+=g_fin[k][idx];
    out[idx]=s;
  }
}

extern "C" void kernel_launch(void* const* d_in, const int* in_sizes, int n_in,
                              void* d_out, int out_size){
  const float* rec1d=(const float*)d_in[0];
  const float* lig1d=(const float*)d_in[1];
  const float* rep  =(const float*)d_in[2];
  const float* recT =(const float*)d_in[3];
  const float* ligT =(const float*)d_in[4];
  const float* rw1  =(const float*)d_in[5];
  const float* rwp  =(const float*)d_in[6];
  const float* lw1  =(const float*)d_in[7];
  const float* lwp  =(const float*)d_in[8];
  const float* rrw  =(const float*)d_in[9];
  const float* llw  =(const float*)d_in[10];
  const float* rlw  =(const float*)d_in[11];
  const float* lrw  =(const float*)d_in[12];
  const float* fw   =(const float*)d_in[13];
  const float* fbias=(const float*)d_in[14];
  float* out=(float*)d_out;

  static int smem_set = 0;
  int att_smem = (12*WP2 + 2*64*PADc + 2*128*WQP + 16*PP2 + 48 + 12*68) * 4;
  if(!smem_set){
    cudaFuncSetAttribute(k_att, cudaFuncAttributeMaxDynamicSharedMemorySize, att_smem);
    smem_set = 1;
  }

  k_proj   <<<dim3(18,12,2),256>>>(rec1d,lig1d,rw1,rwp,lw1,lwp);
  k_frame  <<<768,192>>>(recT,ligT);
  k_qk     <<<dim3(12,12,12),256>>>();
  k_att    <<<dim3(2,768),512,att_smem>>>(rep,rrw,llw,rlw,lrw);
  k_og     <<<dim3(12,12,2),256>>>();
  k_asm    <<<768,96>>>();
  k_final  <<<dim3(6,12,8),256>>>(fw);
  k_comb   <<<1152,256>>>(fbias,out);
}